// round 1
// baseline (speedup 1.0000x reference)
#include <cuda_runtime.h>
#include <cuda_fp16.h>

#define BH_  32
#define H_   16
#define L_   4096
#define D_   128
#define CH_  128   // rows per chunk (4 blocks of 32)
#define NC_  32    // chunks per (b,h)
#define LDH  136   // shared row stride in halves (even; conflict-free frag loads)
#define EPS_ 1e-6f

// scratch: per-chunk state sums -> exclusive prefix (fp16), Z in fp32
__device__ __half g_S[(size_t)BH_ * NC_ * D_ * D_];
__device__ float  g_Z[(size_t)BH_ * NC_ * D_];

__device__ __forceinline__ void mma16816(float c[4],
    unsigned a0, unsigned a1, unsigned a2, unsigned a3,
    unsigned b0, unsigned b1) {
  asm volatile(
    "mma.sync.aligned.m16n8k16.row.col.f32.f16.f16.f32 "
    "{%0,%1,%2,%3},{%4,%5,%6,%7},{%8,%9},{%0,%1,%2,%3};\n"
    : "+f"(c[0]), "+f"(c[1]), "+f"(c[2]), "+f"(c[3])
    : "r"(a0), "r"(a1), "r"(a2), "r"(a3), "r"(b0), "r"(b1));
}

// phi(x) = clip(elu(x*s+b)+1, 0, 10); elu(y)+1 = y+1 (y>0) else exp(y)
__device__ __forceinline__ float phi_f(float x, float s, float b) {
  float y = fmaf(x, s, b);
  float p = (y > 0.f) ? (y + 1.f) : __expf(y);
  return fminf(p, 10.f);
}

// ---------------------------------------------------------------------------
// pass1: per (bh, chunk) compute S_c = phi_k^T V  (fp16), Z_c = colsum(phi_k)
// ---------------------------------------------------------------------------
extern "C" __global__ void __launch_bounds__(256, 1)
la_pass1(const float* __restrict__ K, const float* __restrict__ V,
         const float* __restrict__ scale, const float* __restrict__ bias) {
  int c = blockIdx.x, bh = blockIdx.y, h = bh & (H_ - 1);
  extern __shared__ char smem[];
  __half* s_kt = (__half*)smem;            // [d][r] transposed phi_k
  __half* s_vt = s_kt + D_ * LDH;          // [e][r] transposed v
  float*  s_sc = (float*)(s_vt + D_ * LDH);
  float*  s_bi = s_sc + D_;
  int tid = threadIdx.x;

  if (tid < 64) {
    ((float2*)s_sc)[tid] = ((const float2*)(scale + h * D_))[tid];
    ((float2*)s_bi)[tid] = ((const float2*)(bias + h * D_))[tid];
  }
  __syncthreads();

  size_t off = ((size_t)bh * L_ + (size_t)c * CH_) * D_;
  const float* kp = K + off;
  const float* vp = V + off;
  for (int i = tid; i < CH_ * 32; i += 256) {
    int r = i >> 5, d0 = (i & 31) << 2;
    union { float4 f4; float f[4]; } kv, vv;
    kv.f4 = *(const float4*)(kp + r * D_ + d0);
    vv.f4 = *(const float4*)(vp + r * D_ + d0);
#pragma unroll
    for (int j = 0; j < 4; j++) {
      s_kt[(d0 + j) * LDH + r] = __float2half(phi_f(kv.f[j], s_sc[d0 + j], s_bi[d0 + j]));
      s_vt[(d0 + j) * LDH + r] = __float2half(vv.f[j]);
    }
  }
  __syncthreads();

  int w = tid >> 5, lane = tid & 31, g = lane >> 2, t = lane & 3;
  int m0 = w << 4;  // warp's 16 d-rows of S
  float acc[16][4];
#pragma unroll
  for (int jt = 0; jt < 16; jt++) { acc[jt][0] = acc[jt][1] = acc[jt][2] = acc[jt][3] = 0.f; }

#pragma unroll
  for (int k0 = 0; k0 < CH_; k0 += 16) {
    // A = phi_k^T : [m=d][k=r] natural in s_kt
    unsigned a0 = *(const unsigned*)(s_kt + (m0 + g) * LDH + k0 + 2 * t);
    unsigned a1 = *(const unsigned*)(s_kt + (m0 + g + 8) * LDH + k0 + 2 * t);
    unsigned a2 = *(const unsigned*)(s_kt + (m0 + g) * LDH + k0 + 2 * t + 8);
    unsigned a3 = *(const unsigned*)(s_kt + (m0 + g + 8) * LDH + k0 + 2 * t + 8);
#pragma unroll
    for (int jt = 0; jt < 16; jt++) {
      // B = v : [k=r][n=e], stored as vt[e][r]
      unsigned b0 = *(const unsigned*)(s_vt + (jt * 8 + g) * LDH + k0 + 2 * t);
      unsigned b1 = *(const unsigned*)(s_vt + (jt * 8 + g) * LDH + k0 + 2 * t + 8);
      mma16816(acc[jt], a0, a1, a2, a3, b0, b1);
    }
  }

  __half* Sp = g_S + ((size_t)bh * NC_ + c) * (D_ * D_);
#pragma unroll
  for (int jt = 0; jt < 16; jt++) {
    int n0 = jt * 8 + 2 * t;
    *(__half2*)(Sp + (m0 + g) * D_ + n0)     = __floats2half2_rn(acc[jt][0], acc[jt][1]);
    *(__half2*)(Sp + (m0 + g + 8) * D_ + n0) = __floats2half2_rn(acc[jt][2], acc[jt][3]);
  }

  if (tid < D_) {  // Z[d] = sum over rows of phi_k
    float z = 0.f;
    const __half2* row = (const __half2*)(s_kt + tid * LDH);
#pragma unroll
    for (int r2 = 0; r2 < CH_ / 2; r2++) { float2 f = __half22float2(row[r2]); z += f.x + f.y; }
    g_Z[((size_t)bh * NC_ + c) * D_ + tid] = z;
  }
}

// ---------------------------------------------------------------------------
// pass2: exclusive prefix over chunks (in place), fp32 accumulation
// ---------------------------------------------------------------------------
extern "C" __global__ void __launch_bounds__(256)
la_pass2() {
  int tid = blockIdx.x * blockDim.x + threadIdx.x;  // BH_*D_*D_ threads
  int bh = tid >> 14;
  int idx = tid & 16383;
  __half* base = g_S + (size_t)bh * NC_ * D_ * D_ + idx;
  float run = 0.f;
#pragma unroll
  for (int c = 0; c < NC_; c++) {
    float tv = __half2float(base[(size_t)c * D_ * D_]);
    base[(size_t)c * D_ * D_] = __float2half(run);
    run += tv;
  }
  if (idx < D_) {
    float* zb = g_Z + (size_t)bh * NC_ * D_ + idx;
    float zr = 0.f;
#pragma unroll
    for (int c = 0; c < NC_; c++) { float tv = zb[(size_t)c * D_]; zb[(size_t)c * D_] = zr; zr += tv; }
  }
}

// ---------------------------------------------------------------------------
// pass3: P = mask(phi_q phi_k^T); out = (P V + phi_q S0) / max(den, eps)
//        den = rowsum(P) + phi_q . Z0
// ---------------------------------------------------------------------------
extern "C" __global__ void __launch_bounds__(256, 1)
la_pass3(const float* __restrict__ Q, const float* __restrict__ K,
         const float* __restrict__ V, const float* __restrict__ scale,
         const float* __restrict__ bias, float* __restrict__ out) {
  int c = blockIdx.x, bh = blockIdx.y, h = bh & (H_ - 1);
  extern __shared__ char smem[];
  __half* s_q  = (__half*)smem;        // [r][d]
  __half* s_k  = s_q  + D_ * LDH;      // [r][d]
  __half* s_vt = s_k  + D_ * LDH;      // [e][r]
  __half* s_St = s_vt + D_ * LDH;      // [e][d]  (S0 transposed)
  __half* s_P  = s_St + D_ * LDH;      // [q][k]
  float* s_sc  = (float*)(s_P + D_ * LDH);
  float* s_bi  = s_sc + D_;
  float* s_z   = s_bi + D_;            // Z0
  float* s_den = s_z + D_;             // phi_q . Z0 per row
  float* s_rs  = s_den + D_;           // rowsum(P) per row
  int tid = threadIdx.x;

  if (tid < 64) {
    ((float2*)s_sc)[tid] = ((const float2*)(scale + h * D_))[tid];
    ((float2*)s_bi)[tid] = ((const float2*)(bias + h * D_))[tid];
  } else if (tid < 128) {
    ((float2*)s_z)[tid - 64] = ((const float2*)(g_Z + ((size_t)bh * NC_ + c) * D_))[tid - 64];
  }
  __syncthreads();

  size_t off = ((size_t)bh * L_ + (size_t)c * CH_) * D_;
  for (int i = tid; i < CH_ * 32; i += 256) {
    int r = i >> 5, d0 = (i & 31) << 2;
    union { float4 f4; float f[4]; } qv, kv, vv;
    qv.f4 = *(const float4*)(Q + off + r * D_ + d0);
    kv.f4 = *(const float4*)(K + off + r * D_ + d0);
    vv.f4 = *(const float4*)(V + off + r * D_ + d0);
#pragma unroll
    for (int j = 0; j < 4; j++) {
      float sj = s_sc[d0 + j], bj = s_bi[d0 + j];
      s_q[r * LDH + d0 + j] = __float2half(phi_f(qv.f[j], sj, bj));
      s_k[r * LDH + d0 + j] = __float2half(phi_f(kv.f[j], sj, bj));
      s_vt[(d0 + j) * LDH + r] = __float2half(vv.f[j]);
    }
  }
  // load S0 (exclusive prefix), transpose into s_St[e][d]
  const __half* Sp = g_S + ((size_t)bh * NC_ + c) * (D_ * D_);
  for (int i = tid; i < D_ * 16; i += 256) {
    int d = i >> 4, e0 = (i & 15) << 3;
    union { uint4 u; __half hh[8]; } pk;
    pk.u = *(const uint4*)(Sp + d * D_ + e0);
#pragma unroll
    for (int j = 0; j < 8; j++) s_St[(e0 + j) * LDH + d] = pk.hh[j];
  }
  __syncthreads();

  // den base: phi_q . Z0 (one thread per row)
  if (tid < D_) {
    float db = 0.f;
    const __half2* rowq = (const __half2*)(s_q + tid * LDH);
#pragma unroll
    for (int d2 = 0; d2 < D_ / 2; d2++) {
      float2 f = __half22float2(rowq[d2]);
      db += f.x * s_z[2 * d2] + f.y * s_z[2 * d2 + 1];
    }
    s_den[tid] = db;
  }

  int w = tid >> 5, lane = tid & 31, g = lane >> 2, t = lane & 3;
  int m0 = w << 4;
  int qblk = w >> 1;                 // 32-row block index of this warp's rows
  int jmax = 4 * (qblk + 1);         // allowed 8-wide k tiles (block-causal, diag incl.)

  // ---- GEMM1: P = phi_q @ phi_k^T, masked by tile ----
  float p[16][4];
#pragma unroll
  for (int jt = 0; jt < 16; jt++) { p[jt][0] = p[jt][1] = p[jt][2] = p[jt][3] = 0.f; }
#pragma unroll
  for (int k0 = 0; k0 < D_; k0 += 16) {
    unsigned a0 = *(const unsigned*)(s_q + (m0 + g) * LDH + k0 + 2 * t);
    unsigned a1 = *(const unsigned*)(s_q + (m0 + g + 8) * LDH + k0 + 2 * t);
    unsigned a2 = *(const unsigned*)(s_q + (m0 + g) * LDH + k0 + 2 * t + 8);
    unsigned a3 = *(const unsigned*)(s_q + (m0 + g + 8) * LDH + k0 + 2 * t + 8);
#pragma unroll
    for (int jt = 0; jt < 16; jt++) {
      if (jt < jmax) {
        unsigned b0 = *(const unsigned*)(s_k + (jt * 8 + g) * LDH + k0 + 2 * t);
        unsigned b1 = *(const unsigned*)(s_k + (jt * 8 + g) * LDH + k0 + 2 * t + 8);
        mma16816(p[jt], a0, a1, a2, a3, b0, b1);
      }
    }
  }
  // rowsums of masked P (masked tiles are zero)
  float rs0 = 0.f, rs1 = 0.f;
#pragma unroll
  for (int jt = 0; jt < 16; jt++) { rs0 += p[jt][0] + p[jt][1]; rs1 += p[jt][2] + p[jt][3]; }
  rs0 += __shfl_xor_sync(0xffffffffu, rs0, 1);
  rs0 += __shfl_xor_sync(0xffffffffu, rs0, 2);
  rs1 += __shfl_xor_sync(0xffffffffu, rs1, 1);
  rs1 += __shfl_xor_sync(0xffffffffu, rs1, 2);
  if (t == 0) { s_rs[m0 + g] = rs0; s_rs[m0 + g + 8] = rs1; }
  // store P to shared (fp16)
#pragma unroll
  for (int jt = 0; jt < 16; jt++) {
    int n0 = jt * 8 + 2 * t;
    *(__half2*)(s_P + (m0 + g) * LDH + n0)     = __floats2half2_rn(p[jt][0], p[jt][1]);
    *(__half2*)(s_P + (m0 + g + 8) * LDH + n0) = __floats2half2_rn(p[jt][2], p[jt][3]);
  }
  __syncthreads();

  // ---- GEMM3 + GEMM2 into one accumulator: O = phi_q @ S0 + P @ V ----
  float o[16][4];
#pragma unroll
  for (int jt = 0; jt < 16; jt++) { o[jt][0] = o[jt][1] = o[jt][2] = o[jt][3] = 0.f; }
#pragma unroll
  for (int k0 = 0; k0 < D_; k0 += 16) {  // K over d: A = phi_q, B = S0^T[e][d]
    unsigned a0 = *(const unsigned*)(s_q + (m0 + g) * LDH + k0 + 2 * t);
    unsigned a1 = *(const unsigned*)(s_q + (m0 + g + 8) * LDH + k0 + 2 * t);
    unsigned a2 = *(const unsigned*)(s_q + (m0 + g) * LDH + k0 + 2 * t + 8);
    unsigned a3 = *(const unsigned*)(s_q + (m0 + g + 8) * LDH + k0 + 2 * t + 8);
#pragma unroll
    for (int jt = 0; jt < 16; jt++) {
      unsigned b0 = *(const unsigned*)(s_St + (jt * 8 + g) * LDH + k0 + 2 * t);
      unsigned b1 = *(const unsigned*)(s_St + (jt * 8 + g) * LDH + k0 + 2 * t + 8);
      mma16816(o[jt], a0, a1, a2, a3, b0, b1);
    }
  }
#pragma unroll
  for (int k0 = 0; k0 < D_; k0 += 16) {  // K over krow: A = P, B = V^T[e][r]
    unsigned a0 = *(const unsigned*)(s_P + (m0 + g) * LDH + k0 + 2 * t);
    unsigned a1 = *(const unsigned*)(s_P + (m0 + g + 8) * LDH + k0 + 2 * t);
    unsigned a2 = *(const unsigned*)(s_P + (m0 + g) * LDH + k0 + 2 * t + 8);
    unsigned a3 = *(const unsigned*)(s_P + (m0 + g + 8) * LDH + k0 + 2 * t + 8);
#pragma unroll
    for (int jt = 0; jt < 16; jt++) {
      unsigned b0 = *(const unsigned*)(s_vt + (jt * 8 + g) * LDH + k0 + 2 * t);
      unsigned b1 = *(const unsigned*)(s_vt + (jt * 8 + g) * LDH + k0 + 2 * t + 8);
      mma16816(o[jt], a0, a1, a2, a3, b0, b1);
    }
  }

  // epilogue: divide by den, write out
  float inv0 = 1.f / fmaxf(s_den[m0 + g]     + s_rs[m0 + g],     EPS_);
  float inv1 = 1.f / fmaxf(s_den[m0 + g + 8] + s_rs[m0 + g + 8], EPS_);
  float* op = out + off;
#pragma unroll
  for (int jt = 0; jt < 16; jt++) {
    int n0 = jt * 8 + 2 * t;
    float2 v0; v0.x = o[jt][0] * inv0; v0.y = o[jt][1] * inv0;
    float2 v1; v1.x = o[jt][2] * inv1; v1.y = o[jt][3] * inv1;
    *(float2*)(op + (m0 + g) * D_ + n0)     = v0;
    *(float2*)(op + (m0 + g + 8) * D_ + n0) = v1;
  }
}

// ---------------------------------------------------------------------------
#define P1_SMEM (2 * D_ * LDH * 2 + 2 * D_ * 4)
#define P3_SMEM (5 * D_ * LDH * 2 + 5 * D_ * 4)

extern "C" void kernel_launch(void* const* d_in, const int* in_sizes, int n_in,
                              void* d_out, int out_size) {
  (void)in_sizes; (void)n_in; (void)out_size;
  const float* q  = (const float*)d_in[0];
  const float* k  = (const float*)d_in[1];
  const float* v  = (const float*)d_in[2];
  const float* sc = (const float*)d_in[3];
  const float* bi = (const float*)d_in[4];
  float* out = (float*)d_out;

  static bool attrs_set = false;
  if (!attrs_set) {
    cudaFuncSetAttribute(la_pass1, cudaFuncAttributeMaxDynamicSharedMemorySize, P1_SMEM);
    cudaFuncSetAttribute(la_pass3, cudaFuncAttributeMaxDynamicSharedMemorySize, P3_SMEM);
    attrs_set = true;
  }

  la_pass1<<<dim3(NC_, BH_), 256, P1_SMEM>>>(k, v, sc, bi);
  la_pass2<<<(BH_ * D_ * D_) / 256, 256>>>();
  la_pass3<<<dim3(NC_, BH_), 256, P3_SMEM>>>(q, k, v, sc, bi, out);
}

// round 2
// speedup vs baseline: 1.3423x; 1.3423x over previous
#include <cuda_runtime.h>
#include <cuda_fp16.h>

#define BH_  32
#define H_   16
#define L_   4096
#define D_   128
#define CH_  128   // rows per chunk
#define NC_  32    // chunks per (b,h)
#define LDH  136   // shared row stride in halves (272B: conflict-free LDSM phases)
#define EPS_ 1e-6f

// scratch: per-chunk state sums -> exclusive prefix (fp16), Z in fp32
__device__ __half g_S[(size_t)BH_ * NC_ * D_ * D_];
__device__ float  g_Z[(size_t)BH_ * NC_ * D_];

__device__ __forceinline__ unsigned su32(const void* p) {
  return (unsigned)__cvta_generic_to_shared(p);
}
__device__ __forceinline__ void ldsm4(unsigned& r0, unsigned& r1, unsigned& r2, unsigned& r3, unsigned a) {
  asm volatile("ldmatrix.sync.aligned.m8n8.x4.shared.b16 {%0,%1,%2,%3},[%4];"
               : "=r"(r0), "=r"(r1), "=r"(r2), "=r"(r3) : "r"(a));
}
__device__ __forceinline__ void ldsm4t(unsigned& r0, unsigned& r1, unsigned& r2, unsigned& r3, unsigned a) {
  asm volatile("ldmatrix.sync.aligned.m8n8.x4.trans.shared.b16 {%0,%1,%2,%3},[%4];"
               : "=r"(r0), "=r"(r1), "=r"(r2), "=r"(r3) : "r"(a));
}
__device__ __forceinline__ void mma16816(float c[4],
    unsigned a0, unsigned a1, unsigned a2, unsigned a3,
    unsigned b0, unsigned b1) {
  asm volatile(
    "mma.sync.aligned.m16n8k16.row.col.f32.f16.f16.f32 "
    "{%0,%1,%2,%3},{%4,%5,%6,%7},{%8,%9},{%0,%1,%2,%3};\n"
    : "+f"(c[0]), "+f"(c[1]), "+f"(c[2]), "+f"(c[3])
    : "r"(a0), "r"(a1), "r"(a2), "r"(a3), "r"(b0), "r"(b1));
}

// phi(x) = clip(elu(x*s+b)+1, 0, 10)
__device__ __forceinline__ float phi_f(float x, float s, float b) {
  float y = fmaf(x, s, b);
  float p = (y > 0.f) ? (y + 1.f) : __expf(y);
  return fminf(p, 10.f);
}

// ---------------------------------------------------------------------------
// pass1: S_c = phi_k^T V (fp16), Z_c = colsum(phi_k)
// tiles staged ROW-MAJOR; transposed operands via ldmatrix.trans
// ---------------------------------------------------------------------------
extern "C" __global__ void __launch_bounds__(256, 2)
la_pass1(const float* __restrict__ K, const float* __restrict__ V,
         const float* __restrict__ scale, const float* __restrict__ bias) {
  int c = blockIdx.x, bh = blockIdx.y, h = bh & (H_ - 1);
  extern __shared__ char smem[];
  __half* s_k = (__half*)smem;              // [r][d]
  __half* s_v = s_k + CH_ * LDH;            // [r][e]
  float*  s_sc = (float*)(s_v + CH_ * LDH);
  float*  s_bi = s_sc + D_;
  float*  s_z  = s_bi + D_;
  int tid = threadIdx.x;

  if (tid < 64) {
    ((float2*)s_sc)[tid] = ((const float2*)(scale + h * D_))[tid];
    ((float2*)s_bi)[tid] = ((const float2*)(bias + h * D_))[tid];
  }
  if (tid < D_) s_z[tid] = 0.f;
  __syncthreads();

  size_t off = ((size_t)bh * L_ + (size_t)c * CH_) * D_;
  int r0t = tid >> 5, d0 = (tid & 31) << 2;
  float sc0 = s_sc[d0], sc1 = s_sc[d0 + 1], sc2 = s_sc[d0 + 2], sc3 = s_sc[d0 + 3];
  float bi0 = s_bi[d0], bi1 = s_bi[d0 + 1], bi2 = s_bi[d0 + 2], bi3 = s_bi[d0 + 3];
  float z0 = 0.f, z1 = 0.f, z2 = 0.f, z3 = 0.f;
#pragma unroll
  for (int it = 0; it < 16; it++) {
    int r = r0t + 8 * it;
    float4 kv = *(const float4*)(K + off + r * D_ + d0);
    float4 vv = *(const float4*)(V + off + r * D_ + d0);
    float p0 = phi_f(kv.x, sc0, bi0), p1 = phi_f(kv.y, sc1, bi1);
    float p2 = phi_f(kv.z, sc2, bi2), p3 = phi_f(kv.w, sc3, bi3);
    z0 += p0; z1 += p1; z2 += p2; z3 += p3;
    *(__half2*)(s_k + r * LDH + d0)     = __floats2half2_rn(p0, p1);
    *(__half2*)(s_k + r * LDH + d0 + 2) = __floats2half2_rn(p2, p3);
    *(__half2*)(s_v + r * LDH + d0)     = __floats2half2_rn(vv.x, vv.y);
    *(__half2*)(s_v + r * LDH + d0 + 2) = __floats2half2_rn(vv.z, vv.w);
  }
  atomicAdd(&s_z[d0], z0); atomicAdd(&s_z[d0 + 1], z1);
  atomicAdd(&s_z[d0 + 2], z2); atomicAdd(&s_z[d0 + 3], z3);
  __syncthreads();

  int w = tid >> 5, lane = tid & 31, g = lane >> 2, t = lane & 3;
  int m0 = w << 4;
  // A (trans): row = k0 + (lane&7) + 8*(lane>>4), col = m0 + 8*((lane>>3)&1)
  int rA = (lane & 7) + 8 * (lane >> 4), cA = 8 * ((lane >> 3) & 1);
  // B (trans): row = k0 + (lane&7) + 8*((lane>>3)&1), col = n0 + 8*(lane>>4)
  int rB = (lane & 7) + 8 * ((lane >> 3) & 1), cB = 8 * (lane >> 4);
  unsigned aBase = su32(s_k + rA * LDH + m0 + cA);
  unsigned bBase = su32(s_v + rB * LDH + cB);

  float acc[16][4];
#pragma unroll
  for (int jt = 0; jt < 16; jt++) { acc[jt][0] = acc[jt][1] = acc[jt][2] = acc[jt][3] = 0.f; }

#pragma unroll
  for (int k0 = 0; k0 < CH_; k0 += 16) {
    unsigned a0, a1, a2, a3;
    ldsm4t(a0, a1, a2, a3, aBase + (unsigned)(k0 * LDH) * 2);
#pragma unroll
    for (int jp = 0; jp < 8; jp++) {
      unsigned b0, b1, b2, b3;
      ldsm4t(b0, b1, b2, b3, bBase + (unsigned)(k0 * LDH + jp * 16) * 2);
      mma16816(acc[2 * jp],     a0, a1, a2, a3, b0, b1);
      mma16816(acc[2 * jp + 1], a0, a1, a2, a3, b2, b3);
    }
  }

  __half* Sp = g_S + ((size_t)bh * NC_ + c) * (D_ * D_);
#pragma unroll
  for (int jt = 0; jt < 16; jt++) {
    int n0 = jt * 8 + 2 * t;
    *(__half2*)(Sp + (m0 + g) * D_ + n0)     = __floats2half2_rn(acc[jt][0], acc[jt][1]);
    *(__half2*)(Sp + (m0 + g + 8) * D_ + n0) = __floats2half2_rn(acc[jt][2], acc[jt][3]);
  }
  if (tid < D_) g_Z[((size_t)bh * NC_ + c) * D_ + tid] = s_z[tid];
}

// ---------------------------------------------------------------------------
// pass2: exclusive prefix over chunks (in place)
// ---------------------------------------------------------------------------
extern "C" __global__ void __launch_bounds__(256)
la_pass2() {
  int tid = blockIdx.x * blockDim.x + threadIdx.x;
  int bh = tid >> 14;
  int idx = tid & 16383;
  __half* base = g_S + (size_t)bh * NC_ * D_ * D_ + idx;
  float run = 0.f;
#pragma unroll
  for (int c = 0; c < NC_; c++) {
    float tv = __half2float(base[(size_t)c * D_ * D_]);
    base[(size_t)c * D_ * D_] = __float2half(run);
    run += tv;
  }
  if (idx < D_) {
    float* zb = g_Z + (size_t)bh * NC_ * D_ + idx;
    float zr = 0.f;
#pragma unroll
    for (int c = 0; c < NC_; c++) { float tv = zb[(size_t)c * D_]; zb[(size_t)c * D_] = zr; zr += tv; }
  }
}

// ---------------------------------------------------------------------------
// pass3: P = mask(phi_q phi_k^T) kept in REGISTERS; O = P V + phi_q S0;
//        den = rowsum(P) + phi_q.Z0; out = O / max(den, eps)
// ---------------------------------------------------------------------------
extern "C" __global__ void __launch_bounds__(256, 1)
la_pass3(const float* __restrict__ Q, const float* __restrict__ K,
         const float* __restrict__ V, const float* __restrict__ scale,
         const float* __restrict__ bias, float* __restrict__ out) {
  int c = blockIdx.x, bh = blockIdx.y, h = bh & (H_ - 1);
  extern __shared__ char smem[];
  __half* s_q = (__half*)smem;              // [r][d]
  __half* s_k = s_q + CH_ * LDH;            // [r][d]
  __half* s_v = s_k + CH_ * LDH;            // [r][e]
  __half* s_S = s_v + CH_ * LDH;            // [d][e] S0 row-major
  float*  s_sc  = (float*)(s_S + D_ * LDH);
  float*  s_bi  = s_sc + D_;
  float*  s_z   = s_bi + D_;                // Z0
  float*  s_den = s_z + D_;                 // phi_q . Z0 per row
  int tid = threadIdx.x;

  if (tid < 64) {
    ((float2*)s_sc)[tid] = ((const float2*)(scale + h * D_))[tid];
    ((float2*)s_bi)[tid] = ((const float2*)(bias + h * D_))[tid];
  } else if (tid < 128) {
    ((float2*)s_z)[tid - 64] = ((const float2*)(g_Z + ((size_t)bh * NC_ + c) * D_))[tid - 64];
  }
  if (tid < D_) s_den[tid] = 0.f;
  __syncthreads();

  size_t off = ((size_t)bh * L_ + (size_t)c * CH_) * D_;
  int lane = tid & 31;
  {
    int r0t = tid >> 5, d0 = (tid & 31) << 2;
    float sc0 = s_sc[d0], sc1 = s_sc[d0 + 1], sc2 = s_sc[d0 + 2], sc3 = s_sc[d0 + 3];
    float bi0 = s_bi[d0], bi1 = s_bi[d0 + 1], bi2 = s_bi[d0 + 2], bi3 = s_bi[d0 + 3];
    float zz0 = s_z[d0], zz1 = s_z[d0 + 1], zz2 = s_z[d0 + 2], zz3 = s_z[d0 + 3];
#pragma unroll
    for (int it = 0; it < 16; it++) {
      int r = r0t + 8 * it;
      float4 qv = *(const float4*)(Q + off + r * D_ + d0);
      float4 kv = *(const float4*)(K + off + r * D_ + d0);
      float4 vv = *(const float4*)(V + off + r * D_ + d0);
      float q0 = phi_f(qv.x, sc0, bi0), q1 = phi_f(qv.y, sc1, bi1);
      float q2 = phi_f(qv.z, sc2, bi2), q3 = phi_f(qv.w, sc3, bi3);
      float p0 = phi_f(kv.x, sc0, bi0), p1 = phi_f(kv.y, sc1, bi1);
      float p2 = phi_f(kv.z, sc2, bi2), p3 = phi_f(kv.w, sc3, bi3);
      *(__half2*)(s_q + r * LDH + d0)     = __floats2half2_rn(q0, q1);
      *(__half2*)(s_q + r * LDH + d0 + 2) = __floats2half2_rn(q2, q3);
      *(__half2*)(s_k + r * LDH + d0)     = __floats2half2_rn(p0, p1);
      *(__half2*)(s_k + r * LDH + d0 + 2) = __floats2half2_rn(p2, p3);
      *(__half2*)(s_v + r * LDH + d0)     = __floats2half2_rn(vv.x, vv.y);
      *(__half2*)(s_v + r * LDH + d0 + 2) = __floats2half2_rn(vv.z, vv.w);
      // den contribution: phi_q[r] . Z0 — warp-uniform row r
      float qd = q0 * zz0 + q1 * zz1 + q2 * zz2 + q3 * zz3;
#pragma unroll
      for (int s = 16; s; s >>= 1) qd += __shfl_xor_sync(0xffffffffu, qd, s);
      if (lane == 0) atomicAdd(&s_den[r], qd);
    }
  }
  // load S0 row-major
  {
    const __half* Sp = g_S + ((size_t)bh * NC_ + c) * (D_ * D_);
    for (int i = tid; i < D_ * 16; i += 256) {
      int d = i >> 4, e0 = (i & 15) << 3;
      *(uint4*)(s_S + d * LDH + e0) = *(const uint4*)(Sp + d * D_ + e0);
    }
  }
  __syncthreads();

  int w = tid >> 5, g = lane >> 2, t = lane & 3;
  int m0 = w << 4;
  int qblk = w >> 1;
  int jpmax = 2 * (qblk + 1);   // allowed 16-wide k groups (block-causal, diag incl.)

  unsigned aQ = su32(s_q + (m0 + (lane & 15)) * LDH + 8 * (lane >> 4));  // A non-trans
  int rA = (lane & 7) + 8 * (lane >> 4), cA = 8 * ((lane >> 3) & 1);
  int rB = (lane & 7) + 8 * ((lane >> 3) & 1), cB = 8 * (lane >> 4);
  unsigned bK = su32(s_k + rA * LDH + cA);   // B non-trans (row n, col k)
  unsigned bV = su32(s_v + rB * LDH + cB);   // B trans (row k, col n)
  unsigned bS = su32(s_S + rB * LDH + cB);   // B trans

  // ---- GEMM1: P = phi_q @ phi_k^T (block-causal tiles only) ----
  float p[16][4];
#pragma unroll
  for (int jt = 0; jt < 16; jt++) { p[jt][0] = p[jt][1] = p[jt][2] = p[jt][3] = 0.f; }
#pragma unroll
  for (int k0 = 0; k0 < D_; k0 += 16) {
    unsigned a0, a1, a2, a3;
    ldsm4(a0, a1, a2, a3, aQ + (unsigned)k0 * 2);
#pragma unroll
    for (int jp = 0; jp < 8; jp++) {
      if (jp < jpmax) {
        unsigned b0, b1, b2, b3;
        ldsm4(b0, b1, b2, b3, bK + (unsigned)(jp * 16 * LDH + k0) * 2);
        mma16816(p[2 * jp],     a0, a1, a2, a3, b0, b1);
        mma16816(p[2 * jp + 1], a0, a1, a2, a3, b2, b3);
      }
    }
  }
  // rowsums (masked tiles are zero)
  float rs0 = 0.f, rs1 = 0.f;
#pragma unroll
  for (int jt = 0; jt < 16; jt++) { rs0 += p[jt][0] + p[jt][1]; rs1 += p[jt][2] + p[jt][3]; }
  rs0 += __shfl_xor_sync(0xffffffffu, rs0, 1);
  rs0 += __shfl_xor_sync(0xffffffffu, rs0, 2);
  rs1 += __shfl_xor_sync(0xffffffffu, rs1, 1);
  rs1 += __shfl_xor_sync(0xffffffffu, rs1, 2);
  // pack P accumulator directly into A fragments (no smem roundtrip)
  unsigned ph[16][2];
#pragma unroll
  for (int jt = 0; jt < 16; jt++) {
    __half2 h0 = __floats2half2_rn(p[jt][0], p[jt][1]);
    __half2 h1 = __floats2half2_rn(p[jt][2], p[jt][3]);
    ph[jt][0] = *(unsigned*)&h0;
    ph[jt][1] = *(unsigned*)&h1;
  }

  // ---- O = phi_q @ S0 + P @ V ----
  float o[16][4];
#pragma unroll
  for (int jt = 0; jt < 16; jt++) { o[jt][0] = o[jt][1] = o[jt][2] = o[jt][3] = 0.f; }
#pragma unroll
  for (int k0 = 0; k0 < D_; k0 += 16) {   // K over d: A = phi_q, B = S0 (trans)
    unsigned a0, a1, a2, a3;
    ldsm4(a0, a1, a2, a3, aQ + (unsigned)k0 * 2);
#pragma unroll
    for (int jp = 0; jp < 8; jp++) {
      unsigned b0, b1, b2, b3;
      ldsm4t(b0, b1, b2, b3, bS + (unsigned)(k0 * LDH + jp * 16) * 2);
      mma16816(o[2 * jp],     a0, a1, a2, a3, b0, b1);
      mma16816(o[2 * jp + 1], a0, a1, a2, a3, b2, b3);
    }
  }
#pragma unroll
  for (int kt = 0; kt < 8; kt++) {        // K over k-rows: A = P (regs), B = V (trans)
    if (kt < jpmax) {
      unsigned a0 = ph[2 * kt][0], a1 = ph[2 * kt][1];
      unsigned a2 = ph[2 * kt + 1][0], a3 = ph[2 * kt + 1][1];
#pragma unroll
      for (int jp = 0; jp < 8; jp++) {
        unsigned b0, b1, b2, b3;
        ldsm4t(b0, b1, b2, b3, bV + (unsigned)(kt * 16 * LDH + jp * 16) * 2);
        mma16816(o[2 * jp],     a0, a1, a2, a3, b0, b1);
        mma16816(o[2 * jp + 1], a0, a1, a2, a3, b2, b3);
      }
    }
  }

  // epilogue
  float inv0 = 1.f / fmaxf(s_den[m0 + g]     + rs0, EPS_);
  float inv1 = 1.f / fmaxf(s_den[m0 + g + 8] + rs1, EPS_);
  float* op = out + off;
#pragma unroll
  for (int jt = 0; jt < 16; jt++) {
    int n0 = jt * 8 + 2 * t;
    float2 v0; v0.x = o[jt][0] * inv0; v0.y = o[jt][1] * inv0;
    float2 v1; v1.x = o[jt][2] * inv1; v1.y = o[jt][3] * inv1;
    *(float2*)(op + (m0 + g) * D_ + n0)     = v0;
    *(float2*)(op + (m0 + g + 8) * D_ + n0) = v1;
  }
}

// ---------------------------------------------------------------------------
#define P1_SMEM (2 * CH_ * LDH * 2 + 3 * D_ * 4)
#define P3_SMEM ((3 * CH_ + D_) * LDH * 2 + 4 * D_ * 4)

extern "C" void kernel_launch(void* const* d_in, const int* in_sizes, int n_in,
                              void* d_out, int out_size) {
  (void)in_sizes; (void)n_in; (void)out_size;
  const float* q  = (const float*)d_in[0];
  const float* k  = (const float*)d_in[1];
  const float* v  = (const float*)d_in[2];
  const float* sc = (const float*)d_in[3];
  const float* bi = (const float*)d_in[4];
  float* out = (float*)d_out;

  static bool attrs_set = false;
  if (!attrs_set) {
    cudaFuncSetAttribute(la_pass1, cudaFuncAttributeMaxDynamicSharedMemorySize, P1_SMEM);
    cudaFuncSetAttribute(la_pass3, cudaFuncAttributeMaxDynamicSharedMemorySize, P3_SMEM);
    attrs_set = true;
  }

  la_pass1<<<dim3(NC_, BH_), 256, P1_SMEM>>>(k, v, sc, bi);
  la_pass2<<<(BH_ * D_ * D_) / 256, 256>>>();
  la_pass3<<<dim3(NC_, BH_), 256, P3_SMEM>>>(q, k, v, sc, bi, out);
}

// round 3
// speedup vs baseline: 1.7216x; 1.2826x over previous
#include <cuda_runtime.h>
#include <cuda_fp16.h>

#define BH_  32
#define H_   16
#define L_   4096
#define D_   128
#define CH_  128   // rows per chunk
#define NC_  32    // chunks per (b,h)
#define NS_  (NC_ + 1)  // prefix slots (last = total)
#define LDH  136   // shared row stride in halves
#define EPS_ 1e-6f

// scratch: per-chunk state sums -> exclusive prefix (fp16), Z in fp32
__device__ __half g_S[(size_t)BH_ * NS_ * D_ * D_];
__device__ float  g_Z[(size_t)BH_ * NS_ * D_];

__device__ __forceinline__ unsigned su32(const void* p) {
  return (unsigned)__cvta_generic_to_shared(p);
}
__device__ __forceinline__ void ldsm4(unsigned& r0, unsigned& r1, unsigned& r2, unsigned& r3, unsigned a) {
  asm volatile("ldmatrix.sync.aligned.m8n8.x4.shared.b16 {%0,%1,%2,%3},[%4];"
               : "=r"(r0), "=r"(r1), "=r"(r2), "=r"(r3) : "r"(a));
}
__device__ __forceinline__ void ldsm4t(unsigned& r0, unsigned& r1, unsigned& r2, unsigned& r3, unsigned a) {
  asm volatile("ldmatrix.sync.aligned.m8n8.x4.trans.shared.b16 {%0,%1,%2,%3},[%4];"
               : "=r"(r0), "=r"(r1), "=r"(r2), "=r"(r3) : "r"(a));
}
__device__ __forceinline__ void mma16816(float c[4],
    unsigned a0, unsigned a1, unsigned a2, unsigned a3,
    unsigned b0, unsigned b1) {
  asm volatile(
    "mma.sync.aligned.m16n8k16.row.col.f32.f16.f16.f32 "
    "{%0,%1,%2,%3},{%4,%5,%6,%7},{%8,%9},{%0,%1,%2,%3};\n"
    : "+f"(c[0]), "+f"(c[1]), "+f"(c[2]), "+f"(c[3])
    : "r"(a0), "r"(a1), "r"(a2), "r"(a3), "r"(b0), "r"(b1));
}

__device__ __forceinline__ float phi_f(float x, float s, float b) {
  float y = fmaf(x, s, b);
  float p = (y > 0.f) ? (y + 1.f) : __expf(y);
  return fminf(p, 10.f);
}

// ---------------------------------------------------------------------------
// pass1: S_c = phi_k^T V (fp16), Z_c = colsum(phi_k)  (unchanged core)
// ---------------------------------------------------------------------------
extern "C" __global__ void __launch_bounds__(256, 2)
la_pass1(const float* __restrict__ K, const float* __restrict__ V,
         const float* __restrict__ scale, const float* __restrict__ bias) {
  int c = blockIdx.x, bh = blockIdx.y, h = bh & (H_ - 1);
  extern __shared__ char smem[];
  __half* s_k = (__half*)smem;              // [r][d]
  __half* s_v = s_k + CH_ * LDH;            // [r][e]
  float*  s_sc = (float*)(s_v + CH_ * LDH);
  float*  s_bi = s_sc + D_;
  float*  s_z  = s_bi + D_;
  int tid = threadIdx.x;

  if (tid < 64) {
    ((float2*)s_sc)[tid] = ((const float2*)(scale + h * D_))[tid];
    ((float2*)s_bi)[tid] = ((const float2*)(bias + h * D_))[tid];
  }
  if (tid < D_) s_z[tid] = 0.f;
  __syncthreads();

  size_t off = ((size_t)bh * L_ + (size_t)c * CH_) * D_;
  int r0t = tid >> 5, d0 = (tid & 31) << 2;
  float sc0 = s_sc[d0], sc1 = s_sc[d0 + 1], sc2 = s_sc[d0 + 2], sc3 = s_sc[d0 + 3];
  float bi0 = s_bi[d0], bi1 = s_bi[d0 + 1], bi2 = s_bi[d0 + 2], bi3 = s_bi[d0 + 3];
  float z0 = 0.f, z1 = 0.f, z2 = 0.f, z3 = 0.f;
#pragma unroll
  for (int it = 0; it < 16; it++) {
    int r = r0t + 8 * it;
    float4 kv = *(const float4*)(K + off + r * D_ + d0);
    float4 vv = *(const float4*)(V + off + r * D_ + d0);
    float p0 = phi_f(kv.x, sc0, bi0), p1 = phi_f(kv.y, sc1, bi1);
    float p2 = phi_f(kv.z, sc2, bi2), p3 = phi_f(kv.w, sc3, bi3);
    z0 += p0; z1 += p1; z2 += p2; z3 += p3;
    *(__half2*)(s_k + r * LDH + d0)     = __floats2half2_rn(p0, p1);
    *(__half2*)(s_k + r * LDH + d0 + 2) = __floats2half2_rn(p2, p3);
    *(__half2*)(s_v + r * LDH + d0)     = __floats2half2_rn(vv.x, vv.y);
    *(__half2*)(s_v + r * LDH + d0 + 2) = __floats2half2_rn(vv.z, vv.w);
  }
  atomicAdd(&s_z[d0], z0); atomicAdd(&s_z[d0 + 1], z1);
  atomicAdd(&s_z[d0 + 2], z2); atomicAdd(&s_z[d0 + 3], z3);
  __syncthreads();

  int w = tid >> 5, lane = tid & 31, g = lane >> 2, t = lane & 3;
  int m0 = w << 4;
  int rA = (lane & 7) + 8 * (lane >> 4), cA = 8 * ((lane >> 3) & 1);
  int rB = (lane & 7) + 8 * ((lane >> 3) & 1), cB = 8 * (lane >> 4);
  unsigned aBase = su32(s_k + rA * LDH + m0 + cA);
  unsigned bBase = su32(s_v + rB * LDH + cB);

  float acc[16][4];
#pragma unroll
  for (int jt = 0; jt < 16; jt++) { acc[jt][0] = acc[jt][1] = acc[jt][2] = acc[jt][3] = 0.f; }

#pragma unroll
  for (int k0 = 0; k0 < CH_; k0 += 16) {
    unsigned a0, a1, a2, a3;
    ldsm4t(a0, a1, a2, a3, aBase + (unsigned)(k0 * LDH) * 2);
#pragma unroll
    for (int jp = 0; jp < 8; jp++) {
      unsigned b0, b1, b2, b3;
      ldsm4t(b0, b1, b2, b3, bBase + (unsigned)(k0 * LDH + jp * 16) * 2);
      mma16816(acc[2 * jp],     a0, a1, a2, a3, b0, b1);
      mma16816(acc[2 * jp + 1], a0, a1, a2, a3, b2, b3);
    }
  }

  __half* Sp = g_S + ((size_t)bh * NS_ + c) * (D_ * D_);
#pragma unroll
  for (int jt = 0; jt < 16; jt++) {
    int n0 = jt * 8 + 2 * t;
    *(__half2*)(Sp + (m0 + g) * D_ + n0)     = __floats2half2_rn(acc[jt][0], acc[jt][1]);
    *(__half2*)(Sp + (m0 + g + 8) * D_ + n0) = __floats2half2_rn(acc[jt][2], acc[jt][3]);
  }
  if (tid < D_) g_Z[((size_t)bh * NS_ + c) * D_ + tid] = s_z[tid];
}

// ---------------------------------------------------------------------------
// pass2: exclusive prefix over chunks (in place) + total into slot NC_
// ---------------------------------------------------------------------------
extern "C" __global__ void __launch_bounds__(256)
la_pass2() {
  int tid = blockIdx.x * blockDim.x + threadIdx.x;
  int bh = tid >> 14;
  int idx = tid & 16383;
  __half* base = g_S + (size_t)bh * NS_ * (D_ * D_) + idx;
  float run = 0.f;
  float v = __half2float(base[0]);
#pragma unroll
  for (int c = 0; c < NC_; c++) {
    float vn = (c < NC_ - 1) ? __half2float(base[(size_t)(c + 1) * D_ * D_]) : 0.f;
    base[(size_t)c * D_ * D_] = __float2half(run);
    run += v;
    v = vn;
  }
  base[(size_t)NC_ * D_ * D_] = __float2half(run);
  if (idx < D_) {
    float* zb = g_Z + (size_t)bh * NS_ * D_ + idx;
    float zr = 0.f;
    float zv = zb[0];
#pragma unroll
    for (int c = 0; c < NC_; c++) {
      float zn = (c < NC_ - 1) ? zb[(size_t)(c + 1) * D_] : 0.f;
      zb[(size_t)c * D_] = zr;
      zr += zv;
      zv = zn;
    }
    zb[(size_t)NC_ * D_] = zr;
  }
}

// ---------------------------------------------------------------------------
// pass3: 2 CTAs per 128-row chunk.
//  half=0 (rows 0-63):   O = phi_q @ S0 + P@V          (P over k-blocks <= own)
//  half=1 (rows 64-127): O = phi_q @ S1 - P_fut@V      (P over strict-future blocks)
//  den = phi_q.Z +/- rowsum(P); out = O / max(den, eps)
// ---------------------------------------------------------------------------
extern "C" __global__ void __launch_bounds__(256, 2)
la_pass3(const float* __restrict__ Q, const float* __restrict__ K,
         const float* __restrict__ V, const float* __restrict__ scale,
         const float* __restrict__ bias, float* __restrict__ out) {
  int c = blockIdx.x, bh = blockIdx.y, half = blockIdx.z;
  int h = bh & (H_ - 1);
  extern __shared__ char smem[];
  __half* s_q = (__half*)smem;              // [r][d]  64 rows
  __half* s_k = s_q + 64 * LDH;             // [r][d]  <=64 rows (phi_k)
  __half* s_v = s_k + 64 * LDH;             // [r][e]  <=64 rows
  __half* s_S = s_v + 64 * LDH;             // [d][e]  128 rows
  float*  s_sc  = (float*)(s_S + D_ * LDH);
  float*  s_bi  = s_sc + D_;
  float*  s_z   = s_bi + D_;                // Z (slot c+half)
  float*  s_den = s_z + D_;                 // phi_q . Z per local row (64)
  int tid = threadIdx.x;
  int lane = tid & 31;

  if (tid < 64) {
    ((float2*)s_sc)[tid] = ((const float2*)(scale + h * D_))[tid];
    ((float2*)s_bi)[tid] = ((const float2*)(bias + h * D_))[tid];
    s_den[tid] = 0.f;
  } else if (tid < 128) {
    ((float2*)s_z)[tid - 64] =
      ((const float2*)(g_Z + ((size_t)bh * NS_ + c + half) * D_))[tid - 64];
  }
  __syncthreads();

  size_t qoff = ((size_t)bh * L_ + (size_t)c * CH_ + half * 64) * D_;
  // k/v rows: half==0 -> chunk rows 0..63 ; half==1 -> chunk rows 96..127
  size_t koff = ((size_t)bh * L_ + (size_t)c * CH_ + (half ? 96 : 0)) * D_;
  int kRows = half ? 32 : 64;

  {
    int r0t = tid >> 5, d0 = (tid & 31) << 2;
    float sc0 = s_sc[d0], sc1 = s_sc[d0 + 1], sc2 = s_sc[d0 + 2], sc3 = s_sc[d0 + 3];
    float bi0 = s_bi[d0], bi1 = s_bi[d0 + 1], bi2 = s_bi[d0 + 2], bi3 = s_bi[d0 + 3];
#pragma unroll
    for (int it = 0; it < 8; it++) {   // q rows 0..63
      int r = r0t + 8 * it;
      float4 qv = *(const float4*)(Q + qoff + r * D_ + d0);
      float q0 = phi_f(qv.x, sc0, bi0), q1 = phi_f(qv.y, sc1, bi1);
      float q2 = phi_f(qv.z, sc2, bi2), q3 = phi_f(qv.w, sc3, bi3);
      *(__half2*)(s_q + r * LDH + d0)     = __floats2half2_rn(q0, q1);
      *(__half2*)(s_q + r * LDH + d0 + 2) = __floats2half2_rn(q2, q3);
    }
    for (int it = 0; it < (kRows >> 3); it++) {  // k/v rows
      int r = r0t + 8 * it;
      float4 kv = *(const float4*)(K + koff + r * D_ + d0);
      float4 vv = *(const float4*)(V + koff + r * D_ + d0);
      float p0 = phi_f(kv.x, sc0, bi0), p1 = phi_f(kv.y, sc1, bi1);
      float p2 = phi_f(kv.z, sc2, bi2), p3 = phi_f(kv.w, sc3, bi3);
      *(__half2*)(s_k + r * LDH + d0)     = __floats2half2_rn(p0, p1);
      *(__half2*)(s_k + r * LDH + d0 + 2) = __floats2half2_rn(p2, p3);
      *(__half2*)(s_v + r * LDH + d0)     = __floats2half2_rn(vv.x, vv.y);
      *(__half2*)(s_v + r * LDH + d0 + 2) = __floats2half2_rn(vv.z, vv.w);
    }
  }
  // S (slot c+half) row-major
  {
    const __half* Sp = g_S + ((size_t)bh * NS_ + c + half) * (D_ * D_);
    for (int i = tid; i < D_ * 16; i += 256) {
      int d = i >> 4, e0 = (i & 15) << 3;
      *(uint4*)(s_S + d * LDH + e0) = *(const uint4*)(Sp + d * D_ + e0);
    }
  }
  __syncthreads();

  // den base: phi_q[r] . Z  -- 4 threads per row (conflict-free on s_q)
  {
    int r = tid >> 2, dseg = (tid & 3) << 5;  // 32 d per thread
    float acc = 0.f;
#pragma unroll
    for (int j = 0; j < 16; j++) {
      float2 f = __half22float2(*(const __half2*)(s_q + r * LDH + dseg + 2 * j));
      acc += f.x * s_z[dseg + 2 * j] + f.y * s_z[dseg + 2 * j + 1];
    }
    atomicAdd(&s_den[r], acc);
  }
  __syncthreads();

  int w = tid >> 5, g = lane >> 2, t = lane & 3;
  int mt = w & 3, nh = w >> 2;
  int m0 = mt << 4;
  // jpmax: allowed 16-wide k groups within staged k tile
  int jpmax = half ? (2 * (1 - (mt >> 1))) : (2 * ((mt >> 1) + 1));
  float sgn = half ? -1.f : 1.f;

  unsigned aQ = su32(s_q + (m0 + (lane & 15)) * LDH + 8 * (lane >> 4));
  int rA = (lane & 7) + 8 * (lane >> 4), cA = 8 * ((lane >> 3) & 1);
  int rB = (lane & 7) + 8 * ((lane >> 3) & 1), cB = 8 * (lane >> 4);
  unsigned bK = su32(s_k + rA * LDH + cA);
  unsigned bV = su32(s_v + rB * LDH + nh * 64 + cB);
  unsigned bS = su32(s_S + rB * LDH + nh * 64 + cB);

  // ---- P = phi_q @ phi_k^T over allowed tiles ----
  float p[8][4];
#pragma unroll
  for (int jt = 0; jt < 8; jt++) { p[jt][0] = p[jt][1] = p[jt][2] = p[jt][3] = 0.f; }
  if (jpmax > 0) {
#pragma unroll
    for (int k0 = 0; k0 < D_; k0 += 16) {
      unsigned a0, a1, a2, a3;
      ldsm4(a0, a1, a2, a3, aQ + (unsigned)k0 * 2);
#pragma unroll
      for (int jp = 0; jp < 4; jp++) {
        if (jp < jpmax) {
          unsigned b0, b1, b2, b3;
          ldsm4(b0, b1, b2, b3, bK + (unsigned)(jp * 16 * LDH + k0) * 2);
          mma16816(p[2 * jp],     a0, a1, a2, a3, b0, b1);
          mma16816(p[2 * jp + 1], a0, a1, a2, a3, b2, b3);
        }
      }
    }
  }
  // signed rowsums + signed fp16 pack into A fragments
  float rs0 = 0.f, rs1 = 0.f;
  unsigned ph[8][2];
#pragma unroll
  for (int jt = 0; jt < 8; jt++) {
    float v0 = sgn * p[jt][0], v1 = sgn * p[jt][1];
    float v2 = sgn * p[jt][2], v3 = sgn * p[jt][3];
    rs0 += v0 + v1; rs1 += v2 + v3;
    __half2 h0 = __floats2half2_rn(v0, v1);
    __half2 h1 = __floats2half2_rn(v2, v3);
    ph[jt][0] = *(unsigned*)&h0;
    ph[jt][1] = *(unsigned*)&h1;
  }
  rs0 += __shfl_xor_sync(0xffffffffu, rs0, 1);
  rs0 += __shfl_xor_sync(0xffffffffu, rs0, 2);
  rs1 += __shfl_xor_sync(0xffffffffu, rs1, 1);
  rs1 += __shfl_xor_sync(0xffffffffu, rs1, 2);

  // ---- O = phi_q @ S (+/- P @ V) over this warp's n-half ----
  float o[8][4];
#pragma unroll
  for (int jt = 0; jt < 8; jt++) { o[jt][0] = o[jt][1] = o[jt][2] = o[jt][3] = 0.f; }
#pragma unroll
  for (int k0 = 0; k0 < D_; k0 += 16) {
    unsigned a0, a1, a2, a3;
    ldsm4(a0, a1, a2, a3, aQ + (unsigned)k0 * 2);
#pragma unroll
    for (int jp = 0; jp < 4; jp++) {
      unsigned b0, b1, b2, b3;
      ldsm4t(b0, b1, b2, b3, bS + (unsigned)(k0 * LDH + jp * 16) * 2);
      mma16816(o[2 * jp],     a0, a1, a2, a3, b0, b1);
      mma16816(o[2 * jp + 1], a0, a1, a2, a3, b2, b3);
    }
  }
#pragma unroll
  for (int kt = 0; kt < 4; kt++) {
    if (kt < jpmax) {
      unsigned a0 = ph[2 * kt][0], a1 = ph[2 * kt][1];
      unsigned a2 = ph[2 * kt + 1][0], a3 = ph[2 * kt + 1][1];
#pragma unroll
      for (int jp = 0; jp < 4; jp++) {
        unsigned b0, b1, b2, b3;
        ldsm4t(b0, b1, b2, b3, bV + (unsigned)(kt * 16 * LDH + jp * 16) * 2);
        mma16816(o[2 * jp],     a0, a1, a2, a3, b0, b1);
        mma16816(o[2 * jp + 1], a0, a1, a2, a3, b2, b3);
      }
    }
  }

  // epilogue
  float inv0 = 1.f / fmaxf(s_den[m0 + g]     + rs0, EPS_);
  float inv1 = 1.f / fmaxf(s_den[m0 + g + 8] + rs1, EPS_);
  float* op = out + qoff;
#pragma unroll
  for (int jt = 0; jt < 8; jt++) {
    int n0 = nh * 64 + jt * 8 + 2 * t;
    float2 v0; v0.x = o[jt][0] * inv0; v0.y = o[jt][1] * inv0;
    float2 v1; v1.x = o[jt][2] * inv1; v1.y = o[jt][3] * inv1;
    *(float2*)(op + (m0 + g) * D_ + n0)     = v0;
    *(float2*)(op + (m0 + g + 8) * D_ + n0) = v1;
  }
}

// ---------------------------------------------------------------------------
#define P1_SMEM (2 * CH_ * LDH * 2 + 3 * D_ * 4)
#define P3_SMEM ((3 * 64 + D_) * LDH * 2 + (3 * D_ + 64) * 4)

extern "C" void kernel_launch(void* const* d_in, const int* in_sizes, int n_in,
                              void* d_out, int out_size) {
  (void)in_sizes; (void)n_in; (void)out_size;
  const float* q  = (const float*)d_in[0];
  const float* k  = (const float*)d_in[1];
  const float* v  = (const float*)d_in[2];
  const float* sc = (const float*)d_in[3];
  const float* bi = (const float*)d_in[4];
  float* out = (float*)d_out;

  static bool attrs_set = false;
  if (!attrs_set) {
    cudaFuncSetAttribute(la_pass1, cudaFuncAttributeMaxDynamicSharedMemorySize, P1_SMEM);
    cudaFuncSetAttribute(la_pass3, cudaFuncAttributeMaxDynamicSharedMemorySize, P3_SMEM);
    attrs_set = true;
  }

  la_pass1<<<dim3(NC_, BH_), 256, P1_SMEM>>>(k, v, sc, bi);
  la_pass2<<<(BH_ * D_ * D_) / 256, 256>>>();
  la_pass3<<<dim3(NC_, BH_, 2), 256, P3_SMEM>>>(q, k, v, sc, bi, out);
}

// round 5
// speedup vs baseline: 2.2236x; 1.2916x over previous
#include <cuda_runtime.h>
#include <cuda_fp16.h>

#define BH_  32
#define H_   16
#define L_   4096
#define D_   128
#define CH_  128
#define NC_  32
#define NS_  (NC_ + 1)
#define EPS_ 1e-6f

// scratch: per-chunk state sums -> exclusive prefix (fp16), Z in fp32
__device__ __half g_S[(size_t)BH_ * NS_ * D_ * D_];
__device__ float  g_Z[(size_t)BH_ * NS_ * D_];

__device__ __forceinline__ unsigned su32(const void* p) {
  return (unsigned)__cvta_generic_to_shared(p);
}
__device__ __forceinline__ void cpasync16(unsigned dst, const void* src) {
  asm volatile("cp.async.cg.shared.global [%0], [%1], 16;\n" :: "r"(dst), "l"(src));
}
__device__ __forceinline__ void cpcommit() {
  asm volatile("cp.async.commit_group;\n");
}
template<int N> __device__ __forceinline__ void cp_wait() {
  asm volatile("cp.async.wait_group %0;\n" :: "n"(N));
}
__device__ __forceinline__ void ldsm4(unsigned& r0, unsigned& r1, unsigned& r2, unsigned& r3, unsigned a) {
  asm volatile("ldmatrix.sync.aligned.m8n8.x4.shared.b16 {%0,%1,%2,%3},[%4];"
               : "=r"(r0), "=r"(r1), "=r"(r2), "=r"(r3) : "r"(a));
}
__device__ __forceinline__ void ldsm4t(unsigned& r0, unsigned& r1, unsigned& r2, unsigned& r3, unsigned a) {
  asm volatile("ldmatrix.sync.aligned.m8n8.x4.trans.shared.b16 {%0,%1,%2,%3},[%4];"
               : "=r"(r0), "=r"(r1), "=r"(r2), "=r"(r3) : "r"(a));
}
__device__ __forceinline__ void mma16816(float c[4],
    unsigned a0, unsigned a1, unsigned a2, unsigned a3,
    unsigned b0, unsigned b1) {
  asm volatile(
    "mma.sync.aligned.m16n8k16.row.col.f32.f16.f16.f32 "
    "{%0,%1,%2,%3},{%4,%5,%6,%7},{%8,%9},{%0,%1,%2,%3};\n"
    : "+f"(c[0]), "+f"(c[1]), "+f"(c[2]), "+f"(c[3])
    : "r"(a0), "r"(a1), "r"(a2), "r"(a3), "r"(b0), "r"(b1));
}

__device__ __forceinline__ float phi_f(float x, float s, float b) {
  float y = fmaf(x, s, b);
  float p = (y > 0.f) ? (y + 1.f) : __expf(y);
  return fminf(p, 10.f);
}

// Swizzled fp16 tiles: row stride 128 halves; off(r,c) = r*128 + (((c>>3)^(r&7))<<3) + (c&7)

// ---------------------------------------------------------------------------
// pass1: S_c = phi_k^T V (fp16), Z_c = colsum(phi_k)
// cp.async depth-2 pipeline: WAIT -> PROCESS -> ISSUE (per-thread chunk ownership)
// ---------------------------------------------------------------------------
extern "C" __global__ void __launch_bounds__(256, 2)
la_pass1(const float* __restrict__ K, const float* __restrict__ V,
         const float* __restrict__ scale, const float* __restrict__ bias) {
  int c = blockIdx.x, bh = blockIdx.y, h = bh & (H_ - 1);
  extern __shared__ char smem[];
  __half* s_k = (__half*)smem;                 // 16384 B, swizzled 128x128
  __half* s_v = s_k + 128 * 128;               // +16384 B
  char*   zoneB = smem + 65536;                // 2 x 8192 B raw fp32
  float*  s_sc = (float*)(smem + 81920);
  float*  s_bi = s_sc + 128;
  float*  s_z  = s_bi + 128;
  unsigned sb = su32(smem);
  int tid = threadIdx.x, lane = tid & 31;
  size_t off = ((size_t)bh * L_ + (size_t)c * CH_) * D_;

  auto issue = [&](int p) {
    const float* src = (p < 8) ? (K + off + (size_t)p * 2048)
                               : (V + off + (size_t)(p - 8) * 2048);
    unsigned zb = sb + 65536u + (unsigned)(p & 1) * 8192u;
    cpasync16(zb + tid * 16, src + tid * 4);
    cpasync16(zb + (tid + 256) * 16, src + (tid + 256) * 4);
    cpcommit();
  };
  issue(0); issue(1);

  if (tid < 32)       *(float4*)&s_sc[4 * tid]        = *(const float4*)(scale + h * D_ + 4 * tid);
  else if (tid < 64)  *(float4*)&s_bi[4 * (tid - 32)] = *(const float4*)(bias  + h * D_ + 4 * (tid - 32));
  if (tid < 128) s_z[tid] = 0.f;
  __syncthreads();

  int colf = (tid & 31) * 4;
  float4 scv = *(float4*)&s_sc[colf];
  float4 biv = *(float4*)&s_bi[colf];
  float z0 = 0.f, z1 = 0.f, z2 = 0.f, z3 = 0.f;

  for (int p = 0; p < 16; p++) {
    if (p + 1 < 16) cp_wait<1>(); else cp_wait<0>();   // piece p complete
    const float* zone = (const float*)(zoneB + (p & 1) * 8192);
    bool isK = (p < 8);
    __half* dst = isK ? s_k : s_v;
    int rowb = (p & 7) * 16;
#pragma unroll
    for (int j = 0; j < 2; j++) {
      int cch = tid + j * 256;
      int r = cch >> 5;
      float4 f = *(const float4*)(zone + cch * 4);
      float o0, o1, o2, o3;
      if (isK) {
        o0 = phi_f(f.x, scv.x, biv.x); o1 = phi_f(f.y, scv.y, biv.y);
        o2 = phi_f(f.z, scv.z, biv.z); o3 = phi_f(f.w, scv.w, biv.w);
        z0 += o0; z1 += o1; z2 += o2; z3 += o3;
      } else { o0 = f.x; o1 = f.y; o2 = f.z; o3 = f.w; }
      int rowA = rowb + r;
      int grp = (colf >> 3) ^ (rowA & 7);
      __half2 h0 = __floats2half2_rn(o0, o1), h1 = __floats2half2_rn(o2, o3);
      uint2 pk; pk.x = *(unsigned*)&h0; pk.y = *(unsigned*)&h1;
      *(uint2*)(dst + rowA * 128 + (grp << 3) + (colf & 7)) = pk;
    }
    if (p + 2 < 16) issue(p + 2);   // refill this zone only after reads above
  }
  atomicAdd(&s_z[colf], z0); atomicAdd(&s_z[colf + 1], z1);
  atomicAdd(&s_z[colf + 2], z2); atomicAdd(&s_z[colf + 3], z3);
  __syncthreads();

  // mma: S[d][e] = sum_r phi_k[r][d] * v[r][e]
  int w = tid >> 5, g = lane >> 2, t4 = lane & 3;
  int m0 = w << 4;
  int l7 = lane & 7, cb3 = lane >> 4;
  int rA = (lane & 7) + 8 * (lane >> 4);
  int gA = (2 * w + ((lane >> 3) & 1)) ^ l7;
  unsigned aBase = sb + (unsigned)(rA * 256 + gA * 16);
  int rB = (lane & 7) + 8 * ((lane >> 3) & 1);
  unsigned bBase = sb + 32768u + (unsigned)(rB * 256);

  float acc[16][4];
#pragma unroll
  for (int jt = 0; jt < 16; jt++) { acc[jt][0] = acc[jt][1] = acc[jt][2] = acc[jt][3] = 0.f; }

#pragma unroll
  for (int k0 = 0; k0 < 128; k0 += 16) {
    unsigned a0, a1, a2, a3;
    ldsm4t(a0, a1, a2, a3, aBase + (unsigned)(k0 * 256));
#pragma unroll
    for (int jp = 0; jp < 8; jp++) {
      unsigned b0, b1, b2, b3;
      ldsm4t(b0, b1, b2, b3, bBase + (unsigned)(k0 * 256 + (((2 * jp + cb3) ^ l7) << 4)));
      mma16816(acc[2 * jp],     a0, a1, a2, a3, b0, b1);
      mma16816(acc[2 * jp + 1], a0, a1, a2, a3, b2, b3);
    }
  }

  __half* Sp = g_S + ((size_t)bh * NS_ + c) * (D_ * D_);
#pragma unroll
  for (int jt = 0; jt < 16; jt++) {
    int n0 = jt * 8 + 2 * t4;
    *(__half2*)(Sp + (m0 + g) * D_ + n0)     = __floats2half2_rn(acc[jt][0], acc[jt][1]);
    *(__half2*)(Sp + (m0 + g + 8) * D_ + n0) = __floats2half2_rn(acc[jt][2], acc[jt][3]);
  }
  if (tid < 128) g_Z[((size_t)bh * NS_ + c) * D_ + tid] = s_z[tid];
}

// ---------------------------------------------------------------------------
// pass2: exclusive prefix over chunks, vectorized uint4 (8 halves / thread)
// ---------------------------------------------------------------------------
extern "C" __global__ void __launch_bounds__(256)
la_pass2() {
  int t = blockIdx.x * 256 + threadIdx.x;     // 65536 threads
  int bh = t >> 11;
  int idx = (t & 2047) * 8;
  __half* base = g_S + (size_t)bh * NS_ * (D_ * D_) + idx;
  float run[8] = {0.f, 0.f, 0.f, 0.f, 0.f, 0.f, 0.f, 0.f};
  uint4 cur = *(uint4*)base;
#pragma unroll
  for (int s = 0; s < NC_; s++) {
    uint4 nxt = {0, 0, 0, 0};
    if (s < NC_ - 1) nxt = *(uint4*)(base + (size_t)(s + 1) * (D_ * D_));
    const __half2* hp = (const __half2*)&cur;
    float2 f0 = __half22float2(hp[0]), f1 = __half22float2(hp[1]);
    float2 f2 = __half22float2(hp[2]), f3 = __half22float2(hp[3]);
    __half2 o0 = __floats2half2_rn(run[0], run[1]);
    __half2 o1 = __floats2half2_rn(run[2], run[3]);
    __half2 o2 = __floats2half2_rn(run[4], run[5]);
    __half2 o3 = __floats2half2_rn(run[6], run[7]);
    uint4 ov; ov.x = *(unsigned*)&o0; ov.y = *(unsigned*)&o1;
    ov.z = *(unsigned*)&o2; ov.w = *(unsigned*)&o3;
    *(uint4*)(base + (size_t)s * (D_ * D_)) = ov;
    run[0] += f0.x; run[1] += f0.y; run[2] += f1.x; run[3] += f1.y;
    run[4] += f2.x; run[5] += f2.y; run[6] += f3.x; run[7] += f3.y;
    cur = nxt;
  }
  {
    __half2 o0 = __floats2half2_rn(run[0], run[1]);
    __half2 o1 = __floats2half2_rn(run[2], run[3]);
    __half2 o2 = __floats2half2_rn(run[4], run[5]);
    __half2 o3 = __floats2half2_rn(run[6], run[7]);
    uint4 ov; ov.x = *(unsigned*)&o0; ov.y = *(unsigned*)&o1;
    ov.z = *(unsigned*)&o2; ov.w = *(unsigned*)&o3;
    *(uint4*)(base + (size_t)NC_ * (D_ * D_)) = ov;
  }
  if (t < BH_ * 32) {
    int b2 = t >> 5;
    int i4 = (t & 31) * 4;
    float* zb = g_Z + (size_t)b2 * NS_ * D_ + i4;
    float zr0 = 0.f, zr1 = 0.f, zr2 = 0.f, zr3 = 0.f;
    float4 zc = *(float4*)zb;
#pragma unroll
    for (int s = 0; s < NC_; s++) {
      float4 zn = {0.f, 0.f, 0.f, 0.f};
      if (s < NC_ - 1) zn = *(float4*)(zb + (size_t)(s + 1) * D_);
      float4 ov; ov.x = zr0; ov.y = zr1; ov.z = zr2; ov.w = zr3;
      *(float4*)(zb + (size_t)s * D_) = ov;
      zr0 += zc.x; zr1 += zc.y; zr2 += zc.z; zr3 += zc.w;
      zc = zn;
    }
    float4 ov; ov.x = zr0; ov.y = zr1; ov.z = zr2; ov.w = zr3;
    *(float4*)(zb + (size_t)NC_ * D_) = ov;
  }
}

// ---------------------------------------------------------------------------
// pass3: 2 CTAs per 128-row chunk (exclusive / inclusive forms).
// cp.async: S direct (2 groups) + q/k/v raw-fp32 depth-2 WAIT->PROCESS->ISSUE.
// ---------------------------------------------------------------------------
extern "C" __global__ void __launch_bounds__(256, 2)
la_pass3(const float* __restrict__ Q, const float* __restrict__ K,
         const float* __restrict__ V, const float* __restrict__ scale,
         const float* __restrict__ bias, float* __restrict__ out) {
  int c = blockIdx.x, bh = blockIdx.y, half = blockIdx.z;
  int h = bh & (H_ - 1);
  extern __shared__ char smem[];
  __half* s_q = (__half*)smem;                 // 16384 B
  __half* s_k = s_q + 8192;                    // +16384 B
  __half* s_v = s_k + 8192;                    // +16384 B
  __half* s_S = s_v + 8192;                    // +32768 B (offset 49152)
  char*   zoneB = smem + 81920;                // 2 x 8192 B
  float*  s_sc  = (float*)(smem + 98304);
  float*  s_bi  = s_sc + 128;
  float*  s_z   = s_bi + 128;
  float*  s_den = s_z + 128;                   // 64 floats
  unsigned sb = su32(smem);
  int tid = threadIdx.x, lane = tid & 31;

  size_t qoff = ((size_t)bh * L_ + (size_t)c * CH_ + half * 64) * D_;
  size_t koff = ((size_t)bh * L_ + (size_t)c * CH_ + (half ? 96 : 0)) * D_;
  int nk = half ? 2 : 4;
  int P = 4 + 2 * nk;

  // S via cp.async, 2 groups (swizzled dest; chunk ch -> src halves ch*8)
  const __half* Sp = g_S + ((size_t)bh * NS_ + c + half) * (D_ * D_);
  for (int gq = 0; gq < 2; gq++) {
#pragma unroll
    for (int j = 0; j < 4; j++) {
      int ch = gq * 1024 + j * 256 + tid;
      int d = ch >> 4, e8 = ch & 15;
      unsigned dst = sb + 49152u + (unsigned)((d * 128 + ((e8 ^ (d & 7)) << 3)) * 2);
      cpasync16(dst, Sp + ch * 8);
    }
    cpcommit();
  }
  auto issue = [&](int p) {
    const float* src;
    if (p < 4)           src = Q + qoff + (size_t)p * 2048;
    else if (p < 4 + nk) src = K + koff + (size_t)(p - 4) * 2048;
    else                 src = V + koff + (size_t)(p - 4 - nk) * 2048;
    unsigned zb = sb + 81920u + (unsigned)(p & 1) * 8192u;
    cpasync16(zb + tid * 16, src + tid * 4);
    cpasync16(zb + (tid + 256) * 16, src + (tid + 256) * 4);
    cpcommit();
  };
  issue(0); issue(1);

  if (tid < 32)       *(float4*)&s_sc[4 * tid]        = *(const float4*)(scale + h * D_ + 4 * tid);
  else if (tid < 64)  *(float4*)&s_bi[4 * (tid - 32)] = *(const float4*)(bias  + h * D_ + 4 * (tid - 32));
  else if (tid < 96)  *(float4*)&s_z[4 * (tid - 64)]  =
      *(const float4*)(g_Z + ((size_t)bh * NS_ + c + half) * D_ + 4 * (tid - 64));
  if (tid < 64) s_den[tid] = 0.f;
  __syncthreads();

  int colf = (tid & 31) * 4;
  float4 scv = *(float4*)&s_sc[colf];
  float4 biv = *(float4*)&s_bi[colf];

  for (int p = 0; p < P; p++) {
    if (p + 1 < P) cp_wait<1>(); else cp_wait<0>();   // piece p (and S early) done
    const float* zone = (const float*)(zoneB + (p & 1) * 8192);
    __half* dst; int rowb; bool doPhi;
    if (p < 4)           { dst = s_q; rowb = p * 16;            doPhi = true;  }
    else if (p < 4 + nk) { dst = s_k; rowb = (p - 4) * 16;      doPhi = true;  }
    else                 { dst = s_v; rowb = (p - 4 - nk) * 16; doPhi = false; }
#pragma unroll
    for (int j = 0; j < 2; j++) {
      int cch = tid + j * 256;
      int r = cch >> 5;
      float4 f = *(const float4*)(zone + cch * 4);
      float o0, o1, o2, o3;
      if (doPhi) {
        o0 = phi_f(f.x, scv.x, biv.x); o1 = phi_f(f.y, scv.y, biv.y);
        o2 = phi_f(f.z, scv.z, biv.z); o3 = phi_f(f.w, scv.w, biv.w);
      } else { o0 = f.x; o1 = f.y; o2 = f.z; o3 = f.w; }
      int rowA = rowb + r;
      int grp = (colf >> 3) ^ (rowA & 7);
      __half2 h0 = __floats2half2_rn(o0, o1), h1 = __floats2half2_rn(o2, o3);
      uint2 pk; pk.x = *(unsigned*)&h0; pk.y = *(unsigned*)&h1;
      *(uint2*)(dst + rowA * 128 + (grp << 3) + (colf & 7)) = pk;
    }
    if (p + 2 < P) issue(p + 2);   // refill this zone only after reads above
  }
  __syncthreads();

  // den base: phi_q[r] . Z  (4 threads per row, swizzled reads)
  {
    int r = tid >> 2, ds = (tid & 3) << 5;
    float acc = 0.f;
#pragma unroll
    for (int j = 0; j < 16; j++) {
      int col = ds + 2 * j;
      int grp = ((col >> 3) ^ (r & 7));
      float2 f = __half22float2(*(const __half2*)(s_q + r * 128 + (grp << 3) + (col & 7)));
      acc += f.x * s_z[col] + f.y * s_z[col + 1];
    }
    atomicAdd(&s_den[r], acc);
  }
  __syncthreads();

  int w = tid >> 5, g = lane >> 2, t4 = lane & 3;
  int mt = w & 3, nh = w >> 2, m0 = mt << 4;
  int jpmax = half ? (2 * (1 - (mt >> 1))) : (2 * ((mt >> 1) + 1));
  float sgn = half ? -1.f : 1.f;
  int l7 = lane & 7, cb3 = lane >> 4, ca3 = (lane >> 3) & 1;

  int rq = m0 + (lane & 15), rq7 = rq & 7;
  unsigned aQbase = sb + (unsigned)(rq * 256);
  int rA = (lane & 7) + 8 * (lane >> 4);
  unsigned bKbase = sb + 16384u + (unsigned)(rA * 256);
  int rB = (lane & 7) + 8 * ((lane >> 3) & 1);
  unsigned bVbase = sb + 32768u + (unsigned)(rB * 256);
  unsigned bSbase = sb + 49152u + (unsigned)(rB * 256);

  // ---- P = phi_q @ phi_k^T over allowed tiles ----
  float p[8][4];
#pragma unroll
  for (int jt = 0; jt < 8; jt++) { p[jt][0] = p[jt][1] = p[jt][2] = p[jt][3] = 0.f; }
  if (jpmax > 0) {
#pragma unroll
    for (int k0 = 0; k0 < 128; k0 += 16) {
      unsigned a0, a1, a2, a3;
      ldsm4(a0, a1, a2, a3, aQbase + (unsigned)((((k0 >> 3) + cb3) ^ rq7) << 4));
#pragma unroll
      for (int jp = 0; jp < 4; jp++) {
        if (jp < jpmax) {
          unsigned b0, b1, b2, b3;
          ldsm4(b0, b1, b2, b3, bKbase + (unsigned)(jp * 4096 + ((((k0 >> 3) + ca3) ^ l7) << 4)));
          mma16816(p[2 * jp],     a0, a1, a2, a3, b0, b1);
          mma16816(p[2 * jp + 1], a0, a1, a2, a3, b2, b3);
        }
      }
    }
  }
  // signed rowsums + signed fp16 pack into A fragments
  float rs0 = 0.f, rs1 = 0.f;
  unsigned ph[8][2];
#pragma unroll
  for (int jt = 0; jt < 8; jt++) {
    float v0 = sgn * p[jt][0], v1 = sgn * p[jt][1];
    float v2 = sgn * p[jt][2], v3 = sgn * p[jt][3];
    rs0 += v0 + v1; rs1 += v2 + v3;
    __half2 h0 = __floats2half2_rn(v0, v1);
    __half2 h1 = __floats2half2_rn(v2, v3);
    ph[jt][0] = *(unsigned*)&h0;
    ph[jt][1] = *(unsigned*)&h1;
  }
  rs0 += __shfl_xor_sync(0xffffffffu, rs0, 1);
  rs0 += __shfl_xor_sync(0xffffffffu, rs0, 2);
  rs1 += __shfl_xor_sync(0xffffffffu, rs1, 1);
  rs1 += __shfl_xor_sync(0xffffffffu, rs1, 2);

  // ---- O = phi_q @ S (+/- P @ V) on this warp's n-half ----
  float o[8][4];
#pragma unroll
  for (int jt = 0; jt < 8; jt++) { o[jt][0] = o[jt][1] = o[jt][2] = o[jt][3] = 0.f; }
#pragma unroll
  for (int k0 = 0; k0 < 128; k0 += 16) {
    unsigned a0, a1, a2, a3;
    ldsm4(a0, a1, a2, a3, aQbase + (unsigned)((((k0 >> 3) + cb3) ^ rq7) << 4));
#pragma unroll
    for (int jp = 0; jp < 4; jp++) {
      unsigned b0, b1, b2, b3;
      ldsm4t(b0, b1, b2, b3, bSbase + (unsigned)(k0 * 256 + (((nh * 8 + 2 * jp + cb3) ^ l7) << 4)));
      mma16816(o[2 * jp],     a0, a1, a2, a3, b0, b1);
      mma16816(o[2 * jp + 1], a0, a1, a2, a3, b2, b3);
    }
  }
#pragma unroll
  for (int kt = 0; kt < 4; kt++) {
    if (kt < jpmax) {
      unsigned a0 = ph[2 * kt][0], a1 = ph[2 * kt][1];
      unsigned a2 = ph[2 * kt + 1][0], a3 = ph[2 * kt + 1][1];
#pragma unroll
      for (int jp = 0; jp < 4; jp++) {
        unsigned b0, b1, b2, b3;
        ldsm4t(b0, b1, b2, b3, bVbase + (unsigned)(kt * 4096 + (((nh * 8 + 2 * jp + cb3) ^ l7) << 4)));
        mma16816(o[2 * jp],     a0, a1, a2, a3, b0, b1);
        mma16816(o[2 * jp + 1], a0, a1, a2, a3, b2, b3);
      }
    }
  }

  // epilogue
  float inv0 = 1.f / fmaxf(s_den[m0 + g]     + rs0, EPS_);
  float inv1 = 1.f / fmaxf(s_den[m0 + g + 8] + rs1, EPS_);
  float* op = out + qoff;
#pragma unroll
  for (int jt = 0; jt < 8; jt++) {
    int n0 = nh * 64 + jt * 8 + 2 * t4;
    float2 v0; v0.x = o[jt][0] * inv0; v0.y = o[jt][1] * inv0;
    float2 v1; v1.x = o[jt][2] * inv1; v1.y = o[jt][3] * inv1;
    *(float2*)(op + (m0 + g) * D_ + n0)     = v0;
    *(float2*)(op + (m0 + g + 8) * D_ + n0) = v1;
  }
}

// ---------------------------------------------------------------------------
#define P1_SMEM 83456
#define P3_SMEM 100096

extern "C" void kernel_launch(void* const* d_in, const int* in_sizes, int n_in,
                              void* d_out, int out_size) {
  (void)in_sizes; (void)n_in; (void)out_size;
  const float* q  = (const float*)d_in[0];
  const float* k  = (const float*)d_in[1];
  const float* v  = (const float*)d_in[2];
  const float* sc = (const float*)d_in[3];
  const float* bi = (const float*)d_in[4];
  float* out = (float*)d_out;

  static bool attrs_set = false;
  if (!attrs_set) {
    cudaFuncSetAttribute(la_pass1, cudaFuncAttributeMaxDynamicSharedMemorySize, P1_SMEM);
    cudaFuncSetAttribute(la_pass3, cudaFuncAttributeMaxDynamicSharedMemorySize, P3_SMEM);
    attrs_set = true;
  }

  la_pass1<<<dim3(NC_, BH_), 256, P1_SMEM>>>(k, v, sc, bi);
  la_pass2<<<(BH_ * D_ * D_ / 8) / 256, 256>>>();
  la_pass3<<<dim3(NC_, BH_, 2), 256, P3_SMEM>>>(q, k, v, sc, bi, out);
}

// round 8
// speedup vs baseline: 2.4882x; 1.1190x over previous
#include <cuda_runtime.h>
#include <cuda_fp16.h>

#define BH_  32
#define H_   16
#define L_   4096
#define D_   128
#define CH_  128
#define NC_  32
#define NS_  (NC_ + 1)
#define EPS_ 1e-6f

// scratch: per-chunk state sums -> exclusive prefix (fp16), Z in fp32
__device__ __half g_S[(size_t)BH_ * NS_ * D_ * D_];
__device__ float  g_Z[(size_t)BH_ * NS_ * D_];

__device__ __forceinline__ unsigned su32(const void* p) {
  return (unsigned)__cvta_generic_to_shared(p);
}
__device__ __forceinline__ void cpasync16(unsigned dst, const void* src) {
  asm volatile("cp.async.cg.shared.global [%0], [%1], 16;\n" :: "r"(dst), "l"(src));
}
__device__ __forceinline__ void cpcommit() {
  asm volatile("cp.async.commit_group;\n");
}
template<int N> __device__ __forceinline__ void cp_wait() {
  asm volatile("cp.async.wait_group %0;\n" :: "n"(N));
}
__device__ __forceinline__ void ldsm4(unsigned& r0, unsigned& r1, unsigned& r2, unsigned& r3, unsigned a) {
  asm volatile("ldmatrix.sync.aligned.m8n8.x4.shared.b16 {%0,%1,%2,%3},[%4];"
               : "=r"(r0), "=r"(r1), "=r"(r2), "=r"(r3) : "r"(a));
}
__device__ __forceinline__ void ldsm4t(unsigned& r0, unsigned& r1, unsigned& r2, unsigned& r3, unsigned a) {
  asm volatile("ldmatrix.sync.aligned.m8n8.x4.trans.shared.b16 {%0,%1,%2,%3},[%4];"
               : "=r"(r0), "=r"(r1), "=r"(r2), "=r"(r3) : "r"(a));
}
__device__ __forceinline__ void mma16816(float c[4],
    unsigned a0, unsigned a1, unsigned a2, unsigned a3,
    unsigned b0, unsigned b1) {
  asm volatile(
    "mma.sync.aligned.m16n8k16.row.col.f32.f16.f16.f32 "
    "{%0,%1,%2,%3},{%4,%5,%6,%7},{%8,%9},{%0,%1,%2,%3};\n"
    : "+f"(c[0]), "+f"(c[1]), "+f"(c[2]), "+f"(c[3])
    : "r"(a0), "r"(a1), "r"(a2), "r"(a3), "r"(b0), "r"(b1));
}

__device__ __forceinline__ float phi_f(float x, float s, float b) {
  float y = fmaf(x, s, b);
  float p = (y > 0.f) ? (y + 1.f) : __expf(y);
  return fminf(p, 10.f);
}

// Swizzled fp16 tiles: row stride 128 halves; off(r,c) = r*128 + (((c>>3)^(r&7))<<3) + (c&7)

// ---------------------------------------------------------------------------
// pass1: S_c = phi_k^T V (fp16), Z_c = colsum(phi_k)
// cp.async depth-4 pipeline: WAIT -> PROCESS -> ISSUE (per-thread chunk ownership)
// smem: s_k[16KB] s_v[16KB] raw[4x8KB] consts = 99840B
// ---------------------------------------------------------------------------
extern "C" __global__ void __launch_bounds__(256, 2)
la_pass1(const float* __restrict__ K, const float* __restrict__ V,
         const float* __restrict__ scale, const float* __restrict__ bias) {
  int c = blockIdx.x, bh = blockIdx.y, h = bh & (H_ - 1);
  extern __shared__ char smem[];
  __half* s_k = (__half*)smem;                 // 16384 B, swizzled 128x128
  __half* s_v = s_k + 128 * 128;               // +16384 B
  char*   zoneB = smem + 65536;                // 4 x 8192 B raw fp32
  float*  s_sc = (float*)(smem + 98304);
  float*  s_bi = s_sc + 128;
  float*  s_z  = s_bi + 128;
  unsigned sb = su32(smem);
  int tid = threadIdx.x, lane = tid & 31;
  size_t off = ((size_t)bh * L_ + (size_t)c * CH_) * D_;

  auto issue = [&](int p) {
    const float* src = (p < 8) ? (K + off + (size_t)p * 2048)
                               : (V + off + (size_t)(p - 8) * 2048);
    unsigned zb = sb + 65536u + (unsigned)(p & 3) * 8192u;
    cpasync16(zb + tid * 16, src + tid * 4);
    cpasync16(zb + (tid + 256) * 16, src + (tid + 256) * 4);
    cpcommit();
  };
  issue(0); issue(1); issue(2); issue(3);

  if (tid < 32)       *(float4*)&s_sc[4 * tid]        = *(const float4*)(scale + h * D_ + 4 * tid);
  else if (tid < 64)  *(float4*)&s_bi[4 * (tid - 32)] = *(const float4*)(bias  + h * D_ + 4 * (tid - 32));
  if (tid < 128) s_z[tid] = 0.f;
  __syncthreads();

  int colf = (tid & 31) * 4;
  float4 scv = *(float4*)&s_sc[colf];
  float4 biv = *(float4*)&s_bi[colf];
  float z0 = 0.f, z1 = 0.f, z2 = 0.f, z3 = 0.f;

  for (int p = 0; p < 16; p++) {
    int rem = 15 - p;
    if (rem >= 3) cp_wait<3>();
    else if (rem == 2) cp_wait<2>();
    else if (rem == 1) cp_wait<1>();
    else cp_wait<0>();
    const float* zone = (const float*)(zoneB + (p & 3) * 8192);
    bool isK = (p < 8);
    __half* dst = isK ? s_k : s_v;
    int rowb = (p & 7) * 16;
#pragma unroll
    for (int j = 0; j < 2; j++) {
      int cch = tid + j * 256;
      int r = cch >> 5;
      float4 f = *(const float4*)(zone + cch * 4);
      float o0, o1, o2, o3;
      if (isK) {
        o0 = phi_f(f.x, scv.x, biv.x); o1 = phi_f(f.y, scv.y, biv.y);
        o2 = phi_f(f.z, scv.z, biv.z); o3 = phi_f(f.w, scv.w, biv.w);
        z0 += o0; z1 += o1; z2 += o2; z3 += o3;
      } else { o0 = f.x; o1 = f.y; o2 = f.z; o3 = f.w; }
      int rowA = rowb + r;
      int grp = (colf >> 3) ^ (rowA & 7);
      __half2 h0 = __floats2half2_rn(o0, o1), h1 = __floats2half2_rn(o2, o3);
      uint2 pk; pk.x = *(unsigned*)&h0; pk.y = *(unsigned*)&h1;
      *(uint2*)(dst + rowA * 128 + (grp << 3) + (colf & 7)) = pk;
    }
    if (p + 4 < 16) issue(p + 4);   // refill this zone only after reads above
  }
  atomicAdd(&s_z[colf], z0); atomicAdd(&s_z[colf + 1], z1);
  atomicAdd(&s_z[colf + 2], z2); atomicAdd(&s_z[colf + 3], z3);
  __syncthreads();

  // mma: S[d][e] = sum_r phi_k[r][d] * v[r][e]
  int w = tid >> 5, g = lane >> 2, t4 = lane & 3;
  int m0 = w << 4;
  int l7 = lane & 7, cb3 = lane >> 4;
  int rA = (lane & 7) + 8 * (lane >> 4);
  int gA = (2 * w + ((lane >> 3) & 1)) ^ l7;
  unsigned aBase = sb + (unsigned)(rA * 256 + gA * 16);
  int rB = (lane & 7) + 8 * ((lane >> 3) & 1);
  unsigned bBase = sb + 32768u + (unsigned)(rB * 256);

  float acc[16][4];
#pragma unroll
  for (int jt = 0; jt < 16; jt++) { acc[jt][0] = acc[jt][1] = acc[jt][2] = acc[jt][3] = 0.f; }

#pragma unroll
  for (int k0 = 0; k0 < 128; k0 += 16) {
    unsigned a0, a1, a2, a3;
    ldsm4t(a0, a1, a2, a3, aBase + (unsigned)(k0 * 256));
#pragma unroll
    for (int jp = 0; jp < 8; jp++) {
      unsigned b0, b1, b2, b3;
      ldsm4t(b0, b1, b2, b3, bBase + (unsigned)(k0 * 256 + (((2 * jp + cb3) ^ l7) << 4)));
      mma16816(acc[2 * jp],     a0, a1, a2, a3, b0, b1);
      mma16816(acc[2 * jp + 1], a0, a1, a2, a3, b2, b3);
    }
  }

  __half* Sp = g_S + ((size_t)bh * NS_ + c) * (D_ * D_);
#pragma unroll
  for (int jt = 0; jt < 16; jt++) {
    int n0 = jt * 8 + 2 * t4;
    *(__half2*)(Sp + (m0 + g) * D_ + n0)     = __floats2half2_rn(acc[jt][0], acc[jt][1]);
    *(__half2*)(Sp + (m0 + g + 8) * D_ + n0) = __floats2half2_rn(acc[jt][2], acc[jt][3]);
  }
  if (tid < 128) g_Z[((size_t)bh * NS_ + c) * D_ + tid] = s_z[tid];
}

// ---------------------------------------------------------------------------
// pass2: exclusive prefix over chunks, vectorized uint4 (8 halves / thread)
// ---------------------------------------------------------------------------
extern "C" __global__ void __launch_bounds__(256)
la_pass2() {
  int t = blockIdx.x * 256 + threadIdx.x;     // 65536 threads
  int bh = t >> 11;
  int idx = (t & 2047) * 8;
  __half* base = g_S + (size_t)bh * NS_ * (D_ * D_) + idx;
  float run[8] = {0.f, 0.f, 0.f, 0.f, 0.f, 0.f, 0.f, 0.f};
  uint4 cur = *(uint4*)base;
#pragma unroll
  for (int s = 0; s < NC_; s++) {
    uint4 nxt = {0, 0, 0, 0};
    if (s < NC_ - 1) nxt = *(uint4*)(base + (size_t)(s + 1) * (D_ * D_));
    const __half2* hp = (const __half2*)&cur;
    float2 f0 = __half22float2(hp[0]), f1 = __half22float2(hp[1]);
    float2 f2 = __half22float2(hp[2]), f3 = __half22float2(hp[3]);
    __half2 o0 = __floats2half2_rn(run[0], run[1]);
    __half2 o1 = __floats2half2_rn(run[2], run[3]);
    __half2 o2 = __floats2half2_rn(run[4], run[5]);
    __half2 o3 = __floats2half2_rn(run[6], run[7]);
    uint4 ov; ov.x = *(unsigned*)&o0; ov.y = *(unsigned*)&o1;
    ov.z = *(unsigned*)&o2; ov.w = *(unsigned*)&o3;
    *(uint4*)(base + (size_t)s * (D_ * D_)) = ov;
    run[0] += f0.x; run[1] += f0.y; run[2] += f1.x; run[3] += f1.y;
    run[4] += f2.x; run[5] += f2.y; run[6] += f3.x; run[7] += f3.y;
    cur = nxt;
  }
  {
    __half2 o0 = __floats2half2_rn(run[0], run[1]);
    __half2 o1 = __floats2half2_rn(run[2], run[3]);
    __half2 o2 = __floats2half2_rn(run[4], run[5]);
    __half2 o3 = __floats2half2_rn(run[6], run[7]);
    uint4 ov; ov.x = *(unsigned*)&o0; ov.y = *(unsigned*)&o1;
    ov.z = *(unsigned*)&o2; ov.w = *(unsigned*)&o3;
    *(uint4*)(base + (size_t)NC_ * (D_ * D_)) = ov;
  }
  if (t < BH_ * 32) {
    int b2 = t >> 5;
    int i4 = (t & 31) * 4;
    float* zb = g_Z + (size_t)b2 * NS_ * D_ + i4;
    float zr0 = 0.f, zr1 = 0.f, zr2 = 0.f, zr3 = 0.f;
    float4 zc = *(float4*)zb;
#pragma unroll
    for (int s = 0; s < NC_; s++) {
      float4 zn = {0.f, 0.f, 0.f, 0.f};
      if (s < NC_ - 1) zn = *(float4*)(zb + (size_t)(s + 1) * D_);
      float4 ov; ov.x = zr0; ov.y = zr1; ov.z = zr2; ov.w = zr3;
      *(float4*)(zb + (size_t)s * D_) = ov;
      zr0 += zc.x; zr1 += zc.y; zr2 += zc.z; zr3 += zc.w;
      zc = zn;
    }
    float4 ov; ov.x = zr0; ov.y = zr1; ov.z = zr2; ov.w = zr3;
    *(float4*)(zb + (size_t)NC_ * D_) = ov;
  }
}

// ---------------------------------------------------------------------------
// pass3: 2 CTAs per 128-row chunk (exclusive / inclusive forms).
// cp.async: S direct (2 groups) + q/k/v raw-fp32 depth-3 WAIT->PROCESS->ISSUE.
// smem: s_q/k/v[3x16KB] s_S[32KB] raw[3x8KB] consts = 108288B
// ---------------------------------------------------------------------------
extern "C" __global__ void __launch_bounds__(256, 2)
la_pass3(const float* __restrict__ Q, const float* __restrict__ K,
         const float* __restrict__ V, const float* __restrict__ scale,
         const float* __restrict__ bias, float* __restrict__ out) {
  int c = blockIdx.x, bh = blockIdx.y, half = blockIdx.z;
  int h = bh & (H_ - 1);
  extern __shared__ char smem[];
  __half* s_q = (__half*)smem;                 // 16384 B
  __half* s_k = s_q + 8192;                    // +16384 B
  __half* s_v = s_k + 8192;                    // +16384 B
  __half* s_S = s_v + 8192;                    // +32768 B (offset 49152)
  char*   zoneB = smem + 81920;                // 3 x 8192 B
  float*  s_sc  = (float*)(smem + 106496);
  float*  s_bi  = s_sc + 128;
  float*  s_z   = s_bi + 128;
  float*  s_den = s_z + 128;                   // 64 floats
  unsigned sb = su32(smem);
  int tid = threadIdx.x, lane = tid & 31;

  size_t qoff = ((size_t)bh * L_ + (size_t)c * CH_ + half * 64) * D_;
  size_t koff = ((size_t)bh * L_ + (size_t)c * CH_ + (half ? 96 : 0)) * D_;
  int nk = half ? 2 : 4;
  int P = 4 + 2 * nk;

  // S via cp.async, 2 groups (swizzled dest; chunk ch -> src halves ch*8)
  const __half* Sp = g_S + ((size_t)bh * NS_ + c + half) * (D_ * D_);
  for (int gq = 0; gq < 2; gq++) {
#pragma unroll
    for (int j = 0; j < 4; j++) {
      int ch = gq * 1024 + j * 256 + tid;
      int d = ch >> 4, e8 = ch & 15;
      unsigned dst = sb + 49152u + (unsigned)((d * 128 + ((e8 ^ (d & 7)) << 3)) * 2);
      cpasync16(dst, Sp + ch * 8);
    }
    cpcommit();
  }
  auto issue = [&](int p) {
    const float* src;
    if (p < 4)           src = Q + qoff + (size_t)p * 2048;
    else if (p < 4 + nk) src = K + koff + (size_t)(p - 4) * 2048;
    else                 src = V + koff + (size_t)(p - 4 - nk) * 2048;
    unsigned zb = sb + 81920u + (unsigned)(p % 3) * 8192u;
    cpasync16(zb + tid * 16, src + tid * 4);
    cpasync16(zb + (tid + 256) * 16, src + (tid + 256) * 4);
    cpcommit();
  };
  issue(0); issue(1); issue(2);

  if (tid < 32)       *(float4*)&s_sc[4 * tid]        = *(const float4*)(scale + h * D_ + 4 * tid);
  else if (tid < 64)  *(float4*)&s_bi[4 * (tid - 32)] = *(const float4*)(bias  + h * D_ + 4 * (tid - 32));
  else if (tid < 96)  *(float4*)&s_z[4 * (tid - 64)]  =
      *(const float4*)(g_Z + ((size_t)bh * NS_ + c + half) * D_ + 4 * (tid - 64));
  if (tid < 64) s_den[tid] = 0.f;
  __syncthreads();

  int colf = (tid & 31) * 4;
  float4 scv = *(float4*)&s_sc[colf];
  float4 biv = *(float4*)&s_bi[colf];

  for (int p = 0; p < P; p++) {
    int rem = P - 1 - p;
    if (rem >= 2) cp_wait<2>();
    else if (rem == 1) cp_wait<1>();
    else cp_wait<0>();
    const float* zone = (const float*)(zoneB + (p % 3) * 8192);
    __half* dst; int rowb; bool doPhi;
    if (p < 4)           { dst = s_q; rowb = p * 16;            doPhi = true;  }
    else if (p < 4 + nk) { dst = s_k; rowb = (p - 4) * 16;      doPhi = true;  }
    else                 { dst = s_v; rowb = (p - 4 - nk) * 16; doPhi = false; }
#pragma unroll
    for (int j = 0; j < 2; j++) {
      int cch = tid + j * 256;
      int r = cch >> 5;
      float4 f = *(const float4*)(zone + cch * 4);
      float o0, o1, o2, o3;
      if (doPhi) {
        o0 = phi_f(f.x, scv.x, biv.x); o1 = phi_f(f.y, scv.y, biv.y);
        o2 = phi_f(f.z, scv.z, biv.z); o3 = phi_f(f.w, scv.w, biv.w);
      } else { o0 = f.x; o1 = f.y; o2 = f.z; o3 = f.w; }
      int rowA = rowb + r;
      int grp = (colf >> 3) ^ (rowA & 7);
      __half2 h0 = __floats2half2_rn(o0, o1), h1 = __floats2half2_rn(o2, o3);
      uint2 pk; pk.x = *(unsigned*)&h0; pk.y = *(unsigned*)&h1;
      *(uint2*)(dst + rowA * 128 + (grp << 3) + (colf & 7)) = pk;
    }
    if (p + 3 < P) issue(p + 3);   // refill this zone only after reads above
  }
  __syncthreads();

  // den base: phi_q[r] . Z  (4 threads per row, swizzled reads)
  {
    int r = tid >> 2, ds = (tid & 3) << 5;
    float acc = 0.f;
#pragma unroll
    for (int j = 0; j < 16; j++) {
      int col = ds + 2 * j;
      int grp = ((col >> 3) ^ (r & 7));
      float2 f = __half22float2(*(const __half2*)(s_q + r * 128 + (grp << 3) + (col & 7)));
      acc += f.x * s_z[col] + f.y * s_z[col + 1];
    }
    atomicAdd(&s_den[r], acc);
  }
  __syncthreads();

  int w = tid >> 5, g = lane >> 2, t4 = lane & 3;
  int mt = w & 3, nh = w >> 2, m0 = mt << 4;
  int jpmax = half ? (2 * (1 - (mt >> 1))) : (2 * ((mt >> 1) + 1));
  float sgn = half ? -1.f : 1.f;
  int l7 = lane & 7, cb3 = lane >> 4, ca3 = (lane >> 3) & 1;

  int rq = m0 + (lane & 15), rq7 = rq & 7;
  unsigned aQbase = sb + (unsigned)(rq * 256);
  int rA = (lane & 7) + 8 * (lane >> 4);
  unsigned bKbase = sb + 16384u + (unsigned)(rA * 256);
  int rB = (lane & 7) + 8 * ((lane >> 3) & 1);
  unsigned bVbase = sb + 32768u + (unsigned)(rB * 256);
  unsigned bSbase = sb + 49152u + (unsigned)(rB * 256);

  // ---- P = phi_q @ phi_k^T over allowed tiles ----
  float p[8][4];
#pragma unroll
  for (int jt = 0; jt < 8; jt++) { p[jt][0] = p[jt][1] = p[jt][2] = p[jt][3] = 0.f; }
  if (jpmax > 0) {
#pragma unroll
    for (int k0 = 0; k0 < 128; k0 += 16) {
      unsigned a0, a1, a2, a3;
      ldsm4(a0, a1, a2, a3, aQbase + (unsigned)((((k0 >> 3) + cb3) ^ rq7) << 4));
#pragma unroll
      for (int jp = 0; jp < 4; jp++) {
        if (jp < jpmax) {
          unsigned b0, b1, b2, b3;
          ldsm4(b0, b1, b2, b3, bKbase + (unsigned)(jp * 4096 + ((((k0 >> 3) + ca3) ^ l7) << 4)));
          mma16816(p[2 * jp],     a0, a1, a2, a3, b0, b1);
          mma16816(p[2 * jp + 1], a0, a1, a2, a3, b2, b3);
        }
      }
    }
  }
  // signed rowsums + signed fp16 pack into A fragments
  float rs0 = 0.f, rs1 = 0.f;
  unsigned ph[8][2];
#pragma unroll
  for (int jt = 0; jt < 8; jt++) {
    float v0 = sgn * p[jt][0], v1 = sgn * p[jt][1];
    float v2 = sgn * p[jt][2], v3 = sgn * p[jt][3];
    rs0 += v0 + v1; rs1 += v2 + v3;
    __half2 h0 = __floats2half2_rn(v0, v1);
    __half2 h1 = __floats2half2_rn(v2, v3);
    ph[jt][0] = *(unsigned*)&h0;
    ph[jt][1] = *(unsigned*)&h1;
  }
  rs0 += __shfl_xor_sync(0xffffffffu, rs0, 1);
  rs0 += __shfl_xor_sync(0xffffffffu, rs0, 2);
  rs1 += __shfl_xor_sync(0xffffffffu, rs1, 1);
  rs1 += __shfl_xor_sync(0xffffffffu, rs1, 2);

  // ---- O = phi_q @ S (+/- P @ V) on this warp's n-half ----
  float o[8][4];
#pragma unroll
  for (int jt = 0; jt < 8; jt++) { o[jt][0] = o[jt][1] = o[jt][2] = o[jt][3] = 0.f; }
#pragma unroll
  for (int k0 = 0; k0 < 128; k0 += 16) {
    unsigned a0, a1, a2, a3;
    ldsm4(a0, a1, a2, a3, aQbase + (unsigned)((((k0 >> 3) + cb3) ^ rq7) << 4));
#pragma unroll
    for (int jp = 0; jp < 4; jp++) {
      unsigned b0, b1, b2, b3;
      ldsm4t(b0, b1, b2, b3, bSbase + (unsigned)(k0 * 256 + (((nh * 8 + 2 * jp + cb3) ^ l7) << 4)));
      mma16816(o[2 * jp],     a0, a1, a2, a3, b0, b1);
      mma16816(o[2 * jp + 1], a0, a1, a2, a3, b2, b3);
    }
  }
#pragma unroll
  for (int kt = 0; kt < 4; kt++) {
    if (kt < jpmax) {
      unsigned a0 = ph[2 * kt][0], a1 = ph[2 * kt][1];
      unsigned a2 = ph[2 * kt + 1][0], a3 = ph[2 * kt + 1][1];
#pragma unroll
      for (int jp = 0; jp < 4; jp++) {
        unsigned b0, b1, b2, b3;
        ldsm4t(b0, b1, b2, b3, bVbase + (unsigned)(kt * 4096 + (((nh * 8 + 2 * jp + cb3) ^ l7) << 4)));
        mma16816(o[2 * jp],     a0, a1, a2, a3, b0, b1);
        mma16816(o[2 * jp + 1], a0, a1, a2, a3, b2, b3);
      }
    }
  }

  // epilogue
  float inv0 = 1.f / fmaxf(s_den[m0 + g]     + rs0, EPS_);
  float inv1 = 1.f / fmaxf(s_den[m0 + g + 8] + rs1, EPS_);
  float* op = out + qoff;
#pragma unroll
  for (int jt = 0; jt < 8; jt++) {
    int n0 = nh * 64 + jt * 8 + 2 * t4;
    float2 v0; v0.x = o[jt][0] * inv0; v0.y = o[jt][1] * inv0;
    float2 v1; v1.x = o[jt][2] * inv1; v1.y = o[jt][3] * inv1;
    *(float2*)(op + (m0 + g) * D_ + n0)     = v0;
    *(float2*)(op + (m0 + g + 8) * D_ + n0) = v1;
  }
}

// ---------------------------------------------------------------------------
#define P1_SMEM 99840
#define P3_SMEM 108288

extern "C" void kernel_launch(void* const* d_in, const int* in_sizes, int n_in,
                              void* d_out, int out_size) {
  (void)in_sizes; (void)n_in; (void)out_size;
  const float* q  = (const float*)d_in[0];
  const float* k  = (const float*)d_in[1];
  const float* v  = (const float*)d_in[2];
  const float* sc = (const float*)d_in[3];
  const float* bi = (const float*)d_in[4];
  float* out = (float*)d_out;

  static bool attrs_set = false;
  if (!attrs_set) {
    cudaFuncSetAttribute(la_pass1, cudaFuncAttributeMaxDynamicSharedMemorySize, P1_SMEM);
    cudaFuncSetAttribute(la_pass3, cudaFuncAttributeMaxDynamicSharedMemorySize, P3_SMEM);
    attrs_set = true;
  }

  la_pass1<<<dim3(NC_, BH_), 256, P1_SMEM>>>(k, v, sc, bi);
  la_pass2<<<(BH_ * D_ * D_ / 8) / 256, 256>>>();
  la_pass3<<<dim3(NC_, BH_, 2), 256, P3_SMEM>>>(q, k, v, sc, bi, out);
}

// round 9
// speedup vs baseline: 2.6149x; 1.0509x over previous
#include <cuda_runtime.h>
#include <cuda_fp16.h>

#define BH_  32
#define H_   16
#define L_   4096
#define D_   128
#define CH_  128
#define NC_  32
#define NS_  (NC_ + 1)
#define EPS_ 1e-6f

// scratch: per-chunk state sums -> exclusive prefix (fp16), Z in fp32
__device__ __half g_S[(size_t)BH_ * NS_ * D_ * D_];
__device__ float  g_Z[(size_t)BH_ * NS_ * D_];

__device__ __forceinline__ unsigned su32(const void* p) {
  return (unsigned)__cvta_generic_to_shared(p);
}
__device__ __forceinline__ void cpasync16(unsigned dst, const void* src) {
  asm volatile("cp.async.cg.shared.global [%0], [%1], 16;\n" :: "r"(dst), "l"(src));
}
__device__ __forceinline__ void cpcommit() {
  asm volatile("cp.async.commit_group;\n");
}
template<int N> __device__ __forceinline__ void cp_wait() {
  asm volatile("cp.async.wait_group %0;\n" :: "n"(N));
}
__device__ __forceinline__ void ldsm4(unsigned& r0, unsigned& r1, unsigned& r2, unsigned& r3, unsigned a) {
  asm volatile("ldmatrix.sync.aligned.m8n8.x4.shared.b16 {%0,%1,%2,%3},[%4];"
               : "=r"(r0), "=r"(r1), "=r"(r2), "=r"(r3) : "r"(a));
}
__device__ __forceinline__ void ldsm4t(unsigned& r0, unsigned& r1, unsigned& r2, unsigned& r3, unsigned a) {
  asm volatile("ldmatrix.sync.aligned.m8n8.x4.trans.shared.b16 {%0,%1,%2,%3},[%4];"
               : "=r"(r0), "=r"(r1), "=r"(r2), "=r"(r3) : "r"(a));
}
__device__ __forceinline__ void mma16816(float c[4],
    unsigned a0, unsigned a1, unsigned a2, unsigned a3,
    unsigned b0, unsigned b1) {
  asm volatile(
    "mma.sync.aligned.m16n8k16.row.col.f32.f16.f16.f32 "
    "{%0,%1,%2,%3},{%4,%5,%6,%7},{%8,%9},{%0,%1,%2,%3};\n"
    : "+f"(c[0]), "+f"(c[1]), "+f"(c[2]), "+f"(c[3])
    : "r"(a0), "r"(a1), "r"(a2), "r"(a3), "r"(b0), "r"(b1));
}

__device__ __forceinline__ float phi_f(float x, float s, float b) {
  float y = fmaf(x, s, b);
  float p = (y > 0.f) ? (y + 1.f) : __expf(y);
  return fminf(p, 10.f);
}

// Swizzled fp16 tiles: row stride 128 halves; off(r,c) = r*128 + (((c>>3)^(r&7))<<3) + (c&7)

// ---------------------------------------------------------------------------
// pass1: S_c = phi_k^T V (fp16), Z_c = colsum(phi_k)
// Interleaved: pieces ordered K0,V0,K1,V1,...; after pair t -> mma slice k0=16t
// ---------------------------------------------------------------------------
extern "C" __global__ void __launch_bounds__(256, 2)
la_pass1(const float* __restrict__ K, const float* __restrict__ V,
         const float* __restrict__ scale, const float* __restrict__ bias) {
  int c = blockIdx.x, bh = blockIdx.y, h = bh & (H_ - 1);
  extern __shared__ char smem[];
  __half* s_k = (__half*)smem;                 // 16384 B, swizzled 128x128
  __half* s_v = s_k + 128 * 128;               // +16384 B
  char*   zoneB = smem + 65536;                // 4 x 8192 B raw fp32
  float*  s_sc = (float*)(smem + 98304);
  float*  s_bi = s_sc + 128;
  float*  s_z  = s_bi + 128;
  unsigned sb = su32(smem);
  int tid = threadIdx.x, lane = tid & 31;
  size_t off = ((size_t)bh * L_ + (size_t)c * CH_) * D_;

  // piece p: even -> K row-block p/2 ; odd -> V row-block p/2
  auto issue = [&](int p) {
    int t = p >> 1;
    const float* src = ((p & 1) == 0) ? (K + off + (size_t)t * 2048)
                                      : (V + off + (size_t)t * 2048);
    unsigned zb = sb + 65536u + (unsigned)(p & 3) * 8192u;
    cpasync16(zb + tid * 16, src + tid * 4);
    cpasync16(zb + (tid + 256) * 16, src + (tid + 256) * 4);
    cpcommit();
  };
  issue(0); issue(1); issue(2); issue(3);

  if (tid < 32)       *(float4*)&s_sc[4 * tid]        = *(const float4*)(scale + h * D_ + 4 * tid);
  else if (tid < 64)  *(float4*)&s_bi[4 * (tid - 32)] = *(const float4*)(bias  + h * D_ + 4 * (tid - 32));
  if (tid < 128) s_z[tid] = 0.f;
  __syncthreads();

  int colf = (tid & 31) * 4;
  float4 scv = *(float4*)&s_sc[colf];
  float4 biv = *(float4*)&s_bi[colf];
  float z0 = 0.f, z1 = 0.f, z2 = 0.f, z3 = 0.f;

  // mma frag setup
  int w = tid >> 5, g = lane >> 2, t4 = lane & 3;
  int m0 = w << 4;
  int l7 = lane & 7, cb3 = lane >> 4;
  int rA = (lane & 7) + 8 * (lane >> 4);
  int gA = (2 * w + ((lane >> 3) & 1)) ^ l7;
  unsigned aBase = sb + (unsigned)(rA * 256 + gA * 16);
  int rB = (lane & 7) + 8 * ((lane >> 3) & 1);
  unsigned bBase = sb + 32768u + (unsigned)(rB * 256);

  float acc[16][4];
#pragma unroll
  for (int jt = 0; jt < 16; jt++) { acc[jt][0] = acc[jt][1] = acc[jt][2] = acc[jt][3] = 0.f; }

  for (int t = 0; t < 8; t++) {
#pragma unroll
    for (int q = 0; q < 2; q++) {
      int p = 2 * t + q;
      int rem = 15 - p;
      if (rem >= 3) cp_wait<3>();
      else if (rem == 2) cp_wait<2>();
      else if (rem == 1) cp_wait<1>();
      else cp_wait<0>();
      const float* zone = (const float*)(zoneB + (p & 3) * 8192);
      bool isK = (q == 0);
      __half* dst = isK ? s_k : s_v;
      int rowb = t * 16;
#pragma unroll
      for (int j = 0; j < 2; j++) {
        int cch = tid + j * 256;
        int r = cch >> 5;
        float4 f = *(const float4*)(zone + cch * 4);
        float o0, o1, o2, o3;
        if (isK) {
          o0 = phi_f(f.x, scv.x, biv.x); o1 = phi_f(f.y, scv.y, biv.y);
          o2 = phi_f(f.z, scv.z, biv.z); o3 = phi_f(f.w, scv.w, biv.w);
          z0 += o0; z1 += o1; z2 += o2; z3 += o3;
        } else { o0 = f.x; o1 = f.y; o2 = f.z; o3 = f.w; }
        int rowA = rowb + r;
        int grp = (colf >> 3) ^ (rowA & 7);
        __half2 h0 = __floats2half2_rn(o0, o1), h1 = __floats2half2_rn(o2, o3);
        uint2 pk; pk.x = *(unsigned*)&h0; pk.y = *(unsigned*)&h1;
        *(uint2*)(dst + rowA * 128 + (grp << 3) + (colf & 7)) = pk;
      }
      if (p + 4 < 16) issue(p + 4);
    }
    __syncthreads();           // pair t fully staged by all threads
    int k0 = t * 16;
    unsigned a0, a1, a2, a3;
    ldsm4t(a0, a1, a2, a3, aBase + (unsigned)(k0 * 256));
#pragma unroll
    for (int jp = 0; jp < 8; jp++) {
      unsigned b0, b1, b2, b3;
      ldsm4t(b0, b1, b2, b3, bBase + (unsigned)(k0 * 256 + (((2 * jp + cb3) ^ l7) << 4)));
      mma16816(acc[2 * jp],     a0, a1, a2, a3, b0, b1);
      mma16816(acc[2 * jp + 1], a0, a1, a2, a3, b2, b3);
    }
  }

  atomicAdd(&s_z[colf], z0); atomicAdd(&s_z[colf + 1], z1);
  atomicAdd(&s_z[colf + 2], z2); atomicAdd(&s_z[colf + 3], z3);
  __syncthreads();

  __half* Sp = g_S + ((size_t)bh * NS_ + c) * (D_ * D_);
#pragma unroll
  for (int jt = 0; jt < 16; jt++) {
    int n0 = jt * 8 + 2 * t4;
    *(__half2*)(Sp + (m0 + g) * D_ + n0)     = __floats2half2_rn(acc[jt][0], acc[jt][1]);
    *(__half2*)(Sp + (m0 + g + 8) * D_ + n0) = __floats2half2_rn(acc[jt][2], acc[jt][3]);
  }
  if (tid < 128) g_Z[((size_t)bh * NS_ + c) * D_ + tid] = s_z[tid];
}

// ---------------------------------------------------------------------------
// pass2: exclusive prefix over chunks, vectorized uint4 (8 halves / thread)
// ---------------------------------------------------------------------------
extern "C" __global__ void __launch_bounds__(256)
la_pass2() {
  int t = blockIdx.x * 256 + threadIdx.x;     // 65536 threads
  int bh = t >> 11;
  int idx = (t & 2047) * 8;
  __half* base = g_S + (size_t)bh * NS_ * (D_ * D_) + idx;
  float run[8] = {0.f, 0.f, 0.f, 0.f, 0.f, 0.f, 0.f, 0.f};
  uint4 cur = *(uint4*)base;
#pragma unroll
  for (int s = 0; s < NC_; s++) {
    uint4 nxt = {0, 0, 0, 0};
    if (s < NC_ - 1) nxt = *(uint4*)(base + (size_t)(s + 1) * (D_ * D_));
    const __half2* hp = (const __half2*)&cur;
    float2 f0 = __half22float2(hp[0]), f1 = __half22float2(hp[1]);
    float2 f2 = __half22float2(hp[2]), f3 = __half22float2(hp[3]);
    __half2 o0 = __floats2half2_rn(run[0], run[1]);
    __half2 o1 = __floats2half2_rn(run[2], run[3]);
    __half2 o2 = __floats2half2_rn(run[4], run[5]);
    __half2 o3 = __floats2half2_rn(run[6], run[7]);
    uint4 ov; ov.x = *(unsigned*)&o0; ov.y = *(unsigned*)&o1;
    ov.z = *(unsigned*)&o2; ov.w = *(unsigned*)&o3;
    *(uint4*)(base + (size_t)s * (D_ * D_)) = ov;
    run[0] += f0.x; run[1] += f0.y; run[2] += f1.x; run[3] += f1.y;
    run[4] += f2.x; run[5] += f2.y; run[6] += f3.x; run[7] += f3.y;
    cur = nxt;
  }
  {
    __half2 o0 = __floats2half2_rn(run[0], run[1]);
    __half2 o1 = __floats2half2_rn(run[2], run[3]);
    __half2 o2 = __floats2half2_rn(run[4], run[5]);
    __half2 o3 = __floats2half2_rn(run[6], run[7]);
    uint4 ov; ov.x = *(unsigned*)&o0; ov.y = *(unsigned*)&o1;
    ov.z = *(unsigned*)&o2; ov.w = *(unsigned*)&o3;
    *(uint4*)(base + (size_t)NC_ * (D_ * D_)) = ov;
  }
  if (t < BH_ * 32) {
    int b2 = t >> 5;
    int i4 = (t & 31) * 4;
    float* zb = g_Z + (size_t)b2 * NS_ * D_ + i4;
    float zr0 = 0.f, zr1 = 0.f, zr2 = 0.f, zr3 = 0.f;
    float4 zc = *(float4*)zb;
#pragma unroll
    for (int s = 0; s < NC_; s++) {
      float4 zn = {0.f, 0.f, 0.f, 0.f};
      if (s < NC_ - 1) zn = *(float4*)(zb + (size_t)(s + 1) * D_);
      float4 ov; ov.x = zr0; ov.y = zr1; ov.z = zr2; ov.w = zr3;
      *(float4*)(zb + (size_t)s * D_) = ov;
      zr0 += zc.x; zr1 += zc.y; zr2 += zc.z; zr3 += zc.w;
      zc = zn;
    }
    float4 ov; ov.x = zr0; ov.y = zr1; ov.z = zr2; ov.w = zr3;
    *(float4*)(zb + (size_t)NC_ * D_) = ov;
  }
}

// ---------------------------------------------------------------------------
// pass3: 2 CTAs per 128-row chunk (exclusive / inclusive forms), pipelined:
//   q pieces -> den ; k pieces || O-chunks(0..3) ; v pieces || O(4..7)+P(0..7)
//   -> pack P -> PV gemm -> epilogue
// ---------------------------------------------------------------------------
extern "C" __global__ void __launch_bounds__(256, 2)
la_pass3(const float* __restrict__ Q, const float* __restrict__ K,
         const float* __restrict__ V, const float* __restrict__ scale,
         const float* __restrict__ bias, float* __restrict__ out) {
  int c = blockIdx.x, bh = blockIdx.y, half = blockIdx.z;
  int h = bh & (H_ - 1);
  extern __shared__ char smem[];
  __half* s_q = (__half*)smem;                 // 16384 B
  __half* s_k = s_q + 8192;                    // +16384 B
  __half* s_v = s_k + 8192;                    // +16384 B
  __half* s_S = s_v + 8192;                    // +32768 B (offset 49152)
  char*   zoneB = smem + 81920;                // 3 x 8192 B
  float*  s_sc  = (float*)(smem + 106496);
  float*  s_bi  = s_sc + 128;
  float*  s_z   = s_bi + 128;
  float*  s_den = s_z + 128;                   // 64 floats
  unsigned sb = su32(smem);
  int tid = threadIdx.x, lane = tid & 31;

  size_t qoff = ((size_t)bh * L_ + (size_t)c * CH_ + half * 64) * D_;
  size_t koff = ((size_t)bh * L_ + (size_t)c * CH_ + (half ? 96 : 0)) * D_;
  int nk = half ? 2 : 4;
  int P = 4 + 2 * nk;

  // S via cp.async, 2 groups (complete before piece 0 per FIFO group order)
  const __half* Sp = g_S + ((size_t)bh * NS_ + c + half) * (D_ * D_);
  for (int gq = 0; gq < 2; gq++) {
#pragma unroll
    for (int j = 0; j < 4; j++) {
      int ch = gq * 1024 + j * 256 + tid;
      int d = ch >> 4, e8 = ch & 15;
      unsigned dst = sb + 49152u + (unsigned)((d * 128 + ((e8 ^ (d & 7)) << 3)) * 2);
      cpasync16(dst, Sp + ch * 8);
    }
    cpcommit();
  }
  auto issue = [&](int p) {
    const float* src;
    if (p < 4)           src = Q + qoff + (size_t)p * 2048;
    else if (p < 4 + nk) src = K + koff + (size_t)(p - 4) * 2048;
    else                 src = V + koff + (size_t)(p - 4 - nk) * 2048;
    unsigned zb = sb + 81920u + (unsigned)(p % 3) * 8192u;
    cpasync16(zb + tid * 16, src + tid * 4);
    cpasync16(zb + (tid + 256) * 16, src + (tid + 256) * 4);
    cpcommit();
  };
  issue(0); issue(1); issue(2);

  if (tid < 32)       *(float4*)&s_sc[4 * tid]        = *(const float4*)(scale + h * D_ + 4 * tid);
  else if (tid < 64)  *(float4*)&s_bi[4 * (tid - 32)] = *(const float4*)(bias  + h * D_ + 4 * (tid - 32));
  else if (tid < 96)  *(float4*)&s_z[4 * (tid - 64)]  =
      *(const float4*)(g_Z + ((size_t)bh * NS_ + c + half) * D_ + 4 * (tid - 64));
  if (tid < 64) s_den[tid] = 0.f;
  __syncthreads();

  int colf = (tid & 31) * 4;
  float4 scv = *(float4*)&s_sc[colf];
  float4 biv = *(float4*)&s_bi[colf];

  auto step = [&](int p) {  // wait piece p, convert+store, refill
    int rem = P - 1 - p;
    if (rem >= 2) cp_wait<2>();
    else if (rem == 1) cp_wait<1>();
    else cp_wait<0>();
    const float* zone = (const float*)(zoneB + (p % 3) * 8192);
    __half* dst; int rowb; bool doPhi;
    if (p < 4)           { dst = s_q; rowb = p * 16;            doPhi = true;  }
    else if (p < 4 + nk) { dst = s_k; rowb = (p - 4) * 16;      doPhi = true;  }
    else                 { dst = s_v; rowb = (p - 4 - nk) * 16; doPhi = false; }
#pragma unroll
    for (int j = 0; j < 2; j++) {
      int cch = tid + j * 256;
      int r = cch >> 5;
      float4 f = *(const float4*)(zone + cch * 4);
      float o0, o1, o2, o3;
      if (doPhi) {
        o0 = phi_f(f.x, scv.x, biv.x); o1 = phi_f(f.y, scv.y, biv.y);
        o2 = phi_f(f.z, scv.z, biv.z); o3 = phi_f(f.w, scv.w, biv.w);
      } else { o0 = f.x; o1 = f.y; o2 = f.z; o3 = f.w; }
      int rowA = rowb + r;
      int grp = (colf >> 3) ^ (rowA & 7);
      __half2 h0 = __floats2half2_rn(o0, o1), h1 = __floats2half2_rn(o2, o3);
      uint2 pk; pk.x = *(unsigned*)&h0; pk.y = *(unsigned*)&h1;
      *(uint2*)(dst + rowA * 128 + (grp << 3) + (colf & 7)) = pk;
    }
    if (p + 3 < P) issue(p + 3);
  };

  int w = tid >> 5, g = lane >> 2, t4 = lane & 3;
  int mt = w & 3, nh = w >> 2, m0 = mt << 4;
  int jpmax = half ? (2 * (1 - (mt >> 1))) : (2 * ((mt >> 1) + 1));
  float sgn = half ? -1.f : 1.f;
  int l7 = lane & 7, cb3 = lane >> 4, ca3 = (lane >> 3) & 1;

  int rq = m0 + (lane & 15), rq7 = rq & 7;
  unsigned aQbase = sb + (unsigned)(rq * 256);
  int rA = (lane & 7) + 8 * (lane >> 4);
  unsigned bKbase = sb + 16384u + (unsigned)(rA * 256);
  int rB = (lane & 7) + 8 * ((lane >> 3) & 1);
  unsigned bVbase = sb + 32768u + (unsigned)(rB * 256);
  unsigned bSbase = sb + 49152u + (unsigned)(rB * 256);

  float o[8][4];
  float p_[8][4];
#pragma unroll
  for (int jt = 0; jt < 8; jt++) {
    o[jt][0] = o[jt][1] = o[jt][2] = o[jt][3] = 0.f;
    p_[jt][0] = p_[jt][1] = p_[jt][2] = p_[jt][3] = 0.f;
  }

  auto ochunk = [&](int k0c) {  // O += phi_q(:, k0) @ S(k0, nhalf)
    int k0 = k0c * 16;
    unsigned a0, a1, a2, a3;
    ldsm4(a0, a1, a2, a3, aQbase + (unsigned)(((2 * k0c + cb3) ^ rq7) << 4));
#pragma unroll
    for (int jp = 0; jp < 4; jp++) {
      unsigned b0, b1, b2, b3;
      ldsm4t(b0, b1, b2, b3, bSbase + (unsigned)(k0 * 256 + (((nh * 8 + 2 * jp + cb3) ^ l7) << 4)));
      mma16816(o[2 * jp],     a0, a1, a2, a3, b0, b1);
      mma16816(o[2 * jp + 1], a0, a1, a2, a3, b2, b3);
    }
  };
  auto pchunk = [&](int k0c) {  // P += phi_q(:, k0) @ phi_k(:, k0)^T
    if (jpmax == 0) return;
    unsigned a0, a1, a2, a3;
    ldsm4(a0, a1, a2, a3, aQbase + (unsigned)(((2 * k0c + cb3) ^ rq7) << 4));
#pragma unroll
    for (int jp = 0; jp < 4; jp++) {
      if (jp < jpmax) {
        unsigned b0, b1, b2, b3;
        ldsm4(b0, b1, b2, b3, bKbase + (unsigned)(jp * 4096 + (((2 * k0c + ca3) ^ l7) << 4)));
        mma16816(p_[2 * jp],     a0, a1, a2, a3, b0, b1);
        mma16816(p_[2 * jp + 1], a0, a1, a2, a3, b2, b3);
      }
    }
  };

  // Phase A: q pieces
  step(0); step(1); step(2); step(3);
  __syncthreads();

  // den base: phi_q[r] . Z  (4 threads per row, swizzled reads)
  {
    int r = tid >> 2, ds = (tid & 3) << 5;
    float acc = 0.f;
#pragma unroll
    for (int j = 0; j < 16; j++) {
      int col = ds + 2 * j;
      int grp = ((col >> 3) ^ (r & 7));
      float2 f = __half22float2(*(const __half2*)(s_q + r * 128 + (grp << 3) + (col & 7)));
      acc += f.x * s_z[col] + f.y * s_z[col + 1];
    }
    atomicAdd(&s_den[r], acc);
  }

  // Phase B: k pieces interleaved with O chunks 0..3
  if (half == 0) {
    for (int i = 0; i < 4; i++) { step(4 + i); ochunk(i); }
  } else {
    for (int i = 0; i < 2; i++) { step(4 + i); ochunk(2 * i); ochunk(2 * i + 1); }
  }
  __syncthreads();   // k fully staged

  // Phase C: v pieces interleaved with O chunks 4..7 and P chunks 0..7
  if (half == 0) {
    for (int i = 0; i < 4; i++) {
      step(8 + i); ochunk(4 + i); pchunk(2 * i); pchunk(2 * i + 1);
    }
  } else {
    for (int i = 0; i < 2; i++) {
      step(6 + i); ochunk(4 + 2 * i); ochunk(5 + 2 * i);
      pchunk(4 * i); pchunk(4 * i + 1); pchunk(4 * i + 2); pchunk(4 * i + 3);
    }
  }
  __syncthreads();   // v fully staged

  // signed rowsums + signed fp16 pack of P into A fragments
  float rs0 = 0.f, rs1 = 0.f;
  unsigned ph[8][2];
#pragma unroll
  for (int jt = 0; jt < 8; jt++) {
    float v0 = sgn * p_[jt][0], v1 = sgn * p_[jt][1];
    float v2 = sgn * p_[jt][2], v3 = sgn * p_[jt][3];
    rs0 += v0 + v1; rs1 += v2 + v3;
    __half2 h0 = __floats2half2_rn(v0, v1);
    __half2 h1 = __floats2half2_rn(v2, v3);
    ph[jt][0] = *(unsigned*)&h0;
    ph[jt][1] = *(unsigned*)&h1;
  }
  rs0 += __shfl_xor_sync(0xffffffffu, rs0, 1);
  rs0 += __shfl_xor_sync(0xffffffffu, rs0, 2);
  rs1 += __shfl_xor_sync(0xffffffffu, rs1, 1);
  rs1 += __shfl_xor_sync(0xffffffffu, rs1, 2);

  // PV gemm: O +/- = P @ V
#pragma unroll
  for (int kt = 0; kt < 4; kt++) {
    if (kt < jpmax) {
      unsigned a0 = ph[2 * kt][0], a1 = ph[2 * kt][1];
      unsigned a2 = ph[2 * kt + 1][0], a3 = ph[2 * kt + 1][1];
#pragma unroll
      for (int jp = 0; jp < 4; jp++) {
        unsigned b0, b1, b2, b3;
        ldsm4t(b0, b1, b2, b3, bVbase + (unsigned)(kt * 4096 + (((nh * 8 + 2 * jp + cb3) ^ l7) << 4)));
        mma16816(o[2 * jp],     a0, a1, a2, a3, b0, b1);
        mma16816(o[2 * jp + 1], a0, a1, a2, a3, b2, b3);
      }
    }
  }

  // epilogue
  float inv0 = 1.f / fmaxf(s_den[m0 + g]     + rs0, EPS_);
  float inv1 = 1.f / fmaxf(s_den[m0 + g + 8] + rs1, EPS_);
  float* op = out + qoff;
#pragma unroll
  for (int jt = 0; jt < 8; jt++) {
    int n0 = nh * 64 + jt * 8 + 2 * t4;
    float2 v0; v0.x = o[jt][0] * inv0; v0.y = o[jt][1] * inv0;
    float2 v1; v1.x = o[jt][2] * inv1; v1.y = o[jt][3] * inv1;
    *(float2*)(op + (m0 + g) * D_ + n0)     = v0;
    *(float2*)(op + (m0 + g + 8) * D_ + n0) = v1;
  }
}

// ---------------------------------------------------------------------------
#define P1_SMEM 99840
#define P3_SMEM 108288

extern "C" void kernel_launch(void* const* d_in, const int* in_sizes, int n_in,
                              void* d_out, int out_size) {
  (void)in_sizes; (void)n_in; (void)out_size;
  const float* q  = (const float*)d_in[0];
  const float* k  = (const float*)d_in[1];
  const float* v  = (const float*)d_in[2];
  const float* sc = (const float*)d_in[3];
  const float* bi = (const float*)d_in[4];
  float* out = (float*)d_out;

  static bool attrs_set = false;
  if (!attrs_set) {
    cudaFuncSetAttribute(la_pass1, cudaFuncAttributeMaxDynamicSharedMemorySize, P1_SMEM);
    cudaFuncSetAttribute(la_pass3, cudaFuncAttributeMaxDynamicSharedMemorySize, P3_SMEM);
    attrs_set = true;
  }

  la_pass1<<<dim3(NC_, BH_), 256, P1_SMEM>>>(k, v, sc, bi);
  la_pass2<<<(BH_ * D_ * D_ / 8) / 256, 256>>>();
  la_pass3<<<dim3(NC_, BH_, 2), 256, P3_SMEM>>>(q, k, v, sc, bi, out);
}

// round 11
// speedup vs baseline: 2.6729x; 1.0222x over previous
#include <cuda_runtime.h>
#include <cuda_fp16.h>

#define BH_  32
#define H_   16
#define L_   4096
#define D_   128
#define CH_  128
#define NC_  32
#define NS_  (NC_ + 1)
#define EPS_ 1e-6f

// scratch: per-chunk state sums -> exclusive prefix (fp16), Z in fp32
__device__ __half g_S[(size_t)BH_ * NS_ * D_ * D_];
__device__ float  g_Z[(size_t)BH_ * NS_ * D_];

__device__ __forceinline__ unsigned su32(const void* p) {
  return (unsigned)__cvta_generic_to_shared(p);
}
__device__ __forceinline__ void cpasync16(unsigned dst, const void* src) {
  asm volatile("cp.async.cg.shared.global [%0], [%1], 16;\n" :: "r"(dst), "l"(src));
}
__device__ __forceinline__ void cpcommit() {
  asm volatile("cp.async.commit_group;\n");
}
template<int N> __device__ __forceinline__ void cp_wait() {
  asm volatile("cp.async.wait_group %0;\n" :: "n"(N));
}
__device__ __forceinline__ void ldsm4(unsigned& r0, unsigned& r1, unsigned& r2, unsigned& r3, unsigned a) {
  asm volatile("ldmatrix.sync.aligned.m8n8.x4.shared.b16 {%0,%1,%2,%3},[%4];"
               : "=r"(r0), "=r"(r1), "=r"(r2), "=r"(r3) : "r"(a));
}
__device__ __forceinline__ void ldsm4t(unsigned& r0, unsigned& r1, unsigned& r2, unsigned& r3, unsigned a) {
  asm volatile("ldmatrix.sync.aligned.m8n8.x4.trans.shared.b16 {%0,%1,%2,%3},[%4];"
               : "=r"(r0), "=r"(r1), "=r"(r2), "=r"(r3) : "r"(a));
}
__device__ __forceinline__ void mma16816(float c[4],
    unsigned a0, unsigned a1, unsigned a2, unsigned a3,
    unsigned b0, unsigned b1) {
  asm volatile(
    "mma.sync.aligned.m16n8k16.row.col.f32.f16.f16.f32 "
    "{%0,%1,%2,%3},{%4,%5,%6,%7},{%8,%9},{%0,%1,%2,%3};\n"
    : "+f"(c[0]), "+f"(c[1]), "+f"(c[2]), "+f"(c[3])
    : "r"(a0), "r"(a1), "r"(a2), "r"(a3), "r"(b0), "r"(b1));
}

__device__ __forceinline__ float phi_f(float x, float s, float b) {
  float y = fmaf(x, s, b);
  float p = (y > 0.f) ? (y + 1.f) : __expf(y);
  return fminf(p, 10.f);
}

// Swizzled fp16 tiles: row stride 128 halves; off(r,c) = r*128 + (((c>>3)^(r&7))<<3) + (c&7)

// ---------------------------------------------------------------------------
// pass1: S_c = phi_k^T V (fp16), Z_c = colsum(phi_k)
// Depth-6 cp.async pipeline; pieces K0,V0,K1,V1,...; mma slice after pair t.
// Warp tile m32 x n64 (B-frag duplication 4x instead of 8x).
// smem: s_k[32KB] s_v[32KB] zones[6x8KB] z[512B] = 115200B
// ---------------------------------------------------------------------------
extern "C" __global__ void __launch_bounds__(256, 2)
la_pass1(const float* __restrict__ K, const float* __restrict__ V,
         const float* __restrict__ scale, const float* __restrict__ bias) {
  int c = blockIdx.x, bh = blockIdx.y, h = bh & (H_ - 1);
  extern __shared__ char smem[];
  __half* s_k = (__half*)smem;                 // 32768 B, swizzled 128x128
  __half* s_v = s_k + 128 * 128;               // +32768 B
  char*   zoneB = smem + 65536;                // 6 x 8192 B raw fp32
  float*  s_z  = (float*)(smem + 114688);      // 128 floats
  unsigned sb = su32(smem);
  int tid = threadIdx.x, lane = tid & 31;
  size_t off = ((size_t)bh * L_ + (size_t)c * CH_) * D_;

  // piece p: even -> K row-block p/2 ; odd -> V row-block p/2
  auto issue = [&](int p) {
    int t = p >> 1;
    const float* src = ((p & 1) == 0) ? (K + off + (size_t)t * 2048)
                                      : (V + off + (size_t)t * 2048);
    unsigned zb = sb + 65536u + (unsigned)(p % 6) * 8192u;
    cpasync16(zb + tid * 16, src + tid * 4);
    cpasync16(zb + (tid + 256) * 16, src + (tid + 256) * 4);
    cpcommit();
  };
  issue(0); issue(1); issue(2); issue(3); issue(4); issue(5);

  int colf = (tid & 31) * 4;
  float4 scv = *(const float4*)(scale + h * D_ + colf);  // per-thread consts (L2 hit)
  float4 biv = *(const float4*)(bias  + h * D_ + colf);
  if (tid < 128) s_z[tid] = 0.f;
  float z0 = 0.f, z1 = 0.f, z2 = 0.f, z3 = 0.f;

  // mma frag setup (m32 x n64 warp tile)
  int w = tid >> 5, g = lane >> 2, t4 = lane & 3;
  int wm = w & 3, wn = w >> 2;
  int m0 = wm << 5, n0 = wn << 6;
  int l7 = lane & 7, ca3 = (lane >> 3) & 1, cb3 = lane >> 4;
  int rA = l7 + 8 * cb3;
  int rB = l7 + 8 * ca3;
  unsigned aB0 = sb + (unsigned)(rA * 256 + (((4 * wm + ca3) ^ l7) << 4));
  unsigned aB1 = sb + (unsigned)(rA * 256 + (((4 * wm + 2 + ca3) ^ l7) << 4));
  unsigned bB0 = sb + 32768u + (unsigned)(rB * 256 + (((8 * wn + cb3) ^ l7) << 4));
  unsigned bB1 = sb + 32768u + (unsigned)(rB * 256 + (((8 * wn + 2 + cb3) ^ l7) << 4));
  unsigned bB2 = sb + 32768u + (unsigned)(rB * 256 + (((8 * wn + 4 + cb3) ^ l7) << 4));
  unsigned bB3 = sb + 32768u + (unsigned)(rB * 256 + (((8 * wn + 6 + cb3) ^ l7) << 4));

  float acc[16][4];
#pragma unroll
  for (int jt = 0; jt < 16; jt++) { acc[jt][0] = acc[jt][1] = acc[jt][2] = acc[jt][3] = 0.f; }

  for (int t = 0; t < 8; t++) {
#pragma unroll
    for (int q = 0; q < 2; q++) {
      int p = 2 * t + q;
      int rem = 15 - p;
      if (rem >= 5) cp_wait<5>();
      else if (rem == 4) cp_wait<4>();
      else if (rem == 3) cp_wait<3>();
      else if (rem == 2) cp_wait<2>();
      else if (rem == 1) cp_wait<1>();
      else cp_wait<0>();
      const float* zone = (const float*)(zoneB + (p % 6) * 8192);
      bool isK = (q == 0);
      __half* dst = isK ? s_k : s_v;
      int rowb = t * 16;
#pragma unroll
      for (int j = 0; j < 2; j++) {
        int cch = tid + j * 256;
        int r = cch >> 5;
        float4 f = *(const float4*)(zone + cch * 4);
        float o0, o1, o2, o3;
        if (isK) {
          o0 = phi_f(f.x, scv.x, biv.x); o1 = phi_f(f.y, scv.y, biv.y);
          o2 = phi_f(f.z, scv.z, biv.z); o3 = phi_f(f.w, scv.w, biv.w);
          z0 += o0; z1 += o1; z2 += o2; z3 += o3;
        } else { o0 = f.x; o1 = f.y; o2 = f.z; o3 = f.w; }
        int rowA = rowb + r;
        int grp = (colf >> 3) ^ (rowA & 7);
        __half2 h0 = __floats2half2_rn(o0, o1), h1 = __floats2half2_rn(o2, o3);
        uint2 pk; pk.x = *(unsigned*)&h0; pk.y = *(unsigned*)&h1;
        *(uint2*)(dst + rowA * 128 + (grp << 3) + (colf & 7)) = pk;
      }
      if (p + 6 < 16) issue(p + 6);
    }
    __syncthreads();           // pair t fully staged by all threads
    unsigned ko = (unsigned)(t * 16 * 256);
    unsigned a00, a01, a02, a03, a10, a11, a12, a13;
    ldsm4t(a00, a01, a02, a03, aB0 + ko);   // A subtile ms=0 (d rows m0..m0+15)
    ldsm4t(a10, a11, a12, a13, aB1 + ko);   // A subtile ms=1
    unsigned b0, b1, b2, b3;
    ldsm4t(b0, b1, b2, b3, bB0 + ko);
    mma16816(acc[0], a00, a01, a02, a03, b0, b1);
    mma16816(acc[1], a00, a01, a02, a03, b2, b3);
    mma16816(acc[8], a10, a11, a12, a13, b0, b1);
    mma16816(acc[9], a10, a11, a12, a13, b2, b3);
    ldsm4t(b0, b1, b2, b3, bB1 + ko);
    mma16816(acc[2],  a00, a01, a02, a03, b0, b1);
    mma16816(acc[3],  a00, a01, a02, a03, b2, b3);
    mma16816(acc[10], a10, a11, a12, a13, b0, b1);
    mma16816(acc[11], a10, a11, a12, a13, b2, b3);
    ldsm4t(b0, b1, b2, b3, bB2 + ko);
    mma16816(acc[4],  a00, a01, a02, a03, b0, b1);
    mma16816(acc[5],  a00, a01, a02, a03, b2, b3);
    mma16816(acc[12], a10, a11, a12, a13, b0, b1);
    mma16816(acc[13], a10, a11, a12, a13, b2, b3);
    ldsm4t(b0, b1, b2, b3, bB3 + ko);
    mma16816(acc[6],  a00, a01, a02, a03, b0, b1);
    mma16816(acc[7],  a00, a01, a02, a03, b2, b3);
    mma16816(acc[14], a10, a11, a12, a13, b0, b1);
    mma16816(acc[15], a10, a11, a12, a13, b2, b3);
  }

  atomicAdd(&s_z[colf], z0); atomicAdd(&s_z[colf + 1], z1);
  atomicAdd(&s_z[colf + 2], z2); atomicAdd(&s_z[colf + 3], z3);
  __syncthreads();

  __half* Sp = g_S + ((size_t)bh * NS_ + c) * (D_ * D_);
#pragma unroll
  for (int jt = 0; jt < 16; jt++) {
    int ms = jt >> 3, j = jt & 7;
    int row = m0 + (ms << 4) + g;
    int ncol = n0 + j * 8 + 2 * t4;
    *(__half2*)(Sp + row * D_ + ncol)       = __floats2half2_rn(acc[jt][0], acc[jt][1]);
    *(__half2*)(Sp + (row + 8) * D_ + ncol) = __floats2half2_rn(acc[jt][2], acc[jt][3]);
  }
  if (tid < 128) g_Z[((size_t)bh * NS_ + c) * D_ + tid] = s_z[tid];
}

// ---------------------------------------------------------------------------
// pass2: exclusive prefix over chunks, vectorized uint4 (8 halves / thread)
// ---------------------------------------------------------------------------
extern "C" __global__ void __launch_bounds__(256)
la_pass2() {
  int t = blockIdx.x * 256 + threadIdx.x;     // 65536 threads
  int bh = t >> 11;
  int idx = (t & 2047) * 8;
  __half* base = g_S + (size_t)bh * NS_ * (D_ * D_) + idx;
  float run[8] = {0.f, 0.f, 0.f, 0.f, 0.f, 0.f, 0.f, 0.f};
  uint4 cur = *(uint4*)base;
#pragma unroll
  for (int s = 0; s < NC_; s++) {
    uint4 nxt = {0, 0, 0, 0};
    if (s < NC_ - 1) nxt = *(uint4*)(base + (size_t)(s + 1) * (D_ * D_));
    const __half2* hp = (const __half2*)&cur;
    float2 f0 = __half22float2(hp[0]), f1 = __half22float2(hp[1]);
    float2 f2 = __half22float2(hp[2]), f3 = __half22float2(hp[3]);
    __half2 o0 = __floats2half2_rn(run[0], run[1]);
    __half2 o1 = __floats2half2_rn(run[2], run[3]);
    __half2 o2 = __floats2half2_rn(run[4], run[5]);
    __half2 o3 = __floats2half2_rn(run[6], run[7]);
    uint4 ov; ov.x = *(unsigned*)&o0; ov.y = *(unsigned*)&o1;
    ov.z = *(unsigned*)&o2; ov.w = *(unsigned*)&o3;
    *(uint4*)(base + (size_t)s * (D_ * D_)) = ov;
    run[0] += f0.x; run[1] += f0.y; run[2] += f1.x; run[3] += f1.y;
    run[4] += f2.x; run[5] += f2.y; run[6] += f3.x; run[7] += f3.y;
    cur = nxt;
  }
  {
    __half2 o0 = __floats2half2_rn(run[0], run[1]);
    __half2 o1 = __floats2half2_rn(run[2], run[3]);
    __half2 o2 = __floats2half2_rn(run[4], run[5]);
    __half2 o3 = __floats2half2_rn(run[6], run[7]);
    uint4 ov; ov.x = *(unsigned*)&o0; ov.y = *(unsigned*)&o1;
    ov.z = *(unsigned*)&o2; ov.w = *(unsigned*)&o3;
    *(uint4*)(base + (size_t)NC_ * (D_ * D_)) = ov;
  }
  if (t < BH_ * 32) {
    int b2 = t >> 5;
    int i4 = (t & 31) * 4;
    float* zb = g_Z + (size_t)b2 * NS_ * D_ + i4;
    float zr0 = 0.f, zr1 = 0.f, zr2 = 0.f, zr3 = 0.f;
    float4 zc = *(float4*)zb;
#pragma unroll
    for (int s = 0; s < NC_; s++) {
      float4 zn = {0.f, 0.f, 0.f, 0.f};
      if (s < NC_ - 1) zn = *(float4*)(zb + (size_t)(s + 1) * D_);
      float4 ov; ov.x = zr0; ov.y = zr1; ov.z = zr2; ov.w = zr3;
      *(float4*)(zb + (size_t)s * D_) = ov;
      zr0 += zc.x; zr1 += zc.y; zr2 += zc.z; zr3 += zc.w;
      zc = zn;
    }
    float4 ov; ov.x = zr0; ov.y = zr1; ov.z = zr2; ov.w = zr3;
    *(float4*)(zb + (size_t)NC_ * D_) = ov;
  }
}

// ---------------------------------------------------------------------------
// pass3: 2 CTAs per 128-row chunk (exclusive / inclusive forms), pipelined:
//   q pieces -> den ; k pieces || O-chunks(0..3) ; v pieces || O(4..7)+P(0..7)
//   -> pack P -> PV gemm -> epilogue.   Depth-4 zones.
// smem: s_q[16KB] s_k[16KB] s_v[16KB] s_S[32KB] zones[4x8KB] z+den = 115456B
// ---------------------------------------------------------------------------
extern "C" __global__ void __launch_bounds__(256, 2)
la_pass3(const float* __restrict__ Q, const float* __restrict__ K,
         const float* __restrict__ V, const float* __restrict__ scale,
         const float* __restrict__ bias, float* __restrict__ out) {
  int c = blockIdx.x, bh = blockIdx.y, half = blockIdx.z;
  int h = bh & (H_ - 1);
  extern __shared__ char smem[];
  __half* s_q = (__half*)smem;                 // 16384 B (64 rows)
  __half* s_k = s_q + 8192;                    // +16384 B
  __half* s_v = s_k + 8192;                    // +16384 B
  __half* s_S = s_v + 8192;                    // +32768 B (offset 49152)
  char*   zoneB = smem + 81920;                // 4 x 8192 B
  float*  s_z   = (float*)(smem + 114688);     // 128 floats
  float*  s_den = s_z + 128;                   // 64 floats
  unsigned sb = su32(smem);
  int tid = threadIdx.x, lane = tid & 31;

  size_t qoff = ((size_t)bh * L_ + (size_t)c * CH_ + half * 64) * D_;
  size_t koff = ((size_t)bh * L_ + (size_t)c * CH_ + (half ? 96 : 0)) * D_;
  int nk = half ? 2 : 4;
  int P = 4 + 2 * nk;

  // S via cp.async, 2 groups (complete before piece 0 per FIFO group order)
  const __half* Sp = g_S + ((size_t)bh * NS_ + c + half) * (D_ * D_);
  for (int gq = 0; gq < 2; gq++) {
#pragma unroll
    for (int j = 0; j < 4; j++) {
      int ch = gq * 1024 + j * 256 + tid;
      int d = ch >> 4, e8 = ch & 15;
      unsigned dst = sb + 49152u + (unsigned)((d * 128 + ((e8 ^ (d & 7)) << 3)) * 2);
      cpasync16(dst, Sp + ch * 8);
    }
    cpcommit();
  }
  auto issue = [&](int p) {
    const float* src;
    if (p < 4)           src = Q + qoff + (size_t)p * 2048;
    else if (p < 4 + nk) src = K + koff + (size_t)(p - 4) * 2048;
    else                 src = V + koff + (size_t)(p - 4 - nk) * 2048;
    unsigned zb = sb + 81920u + (unsigned)(p & 3) * 8192u;
    cpasync16(zb + tid * 16, src + tid * 4);
    cpasync16(zb + (tid + 256) * 16, src + (tid + 256) * 4);
    cpcommit();
  };
  issue(0); issue(1); issue(2); issue(3);

  int colf = (tid & 31) * 4;
  float4 scv = *(const float4*)(scale + h * D_ + colf);
  float4 biv = *(const float4*)(bias  + h * D_ + colf);
  if (tid < 32)
    *(float4*)&s_z[4 * tid] =
      *(const float4*)(g_Z + ((size_t)bh * NS_ + c + half) * D_ + 4 * tid);
  if (tid < 64) s_den[tid] = 0.f;

  auto step = [&](int p) {  // wait piece p, convert+store, refill
    int rem = P - 1 - p;
    if (rem >= 3) cp_wait<3>();
    else if (rem == 2) cp_wait<2>();
    else if (rem == 1) cp_wait<1>();
    else cp_wait<0>();
    const float* zone = (const float*)(zoneB + (p & 3) * 8192);
    __half* dst; int rowb; bool doPhi;
    if (p < 4)           { dst = s_q; rowb = p * 16;            doPhi = true;  }
    else if (p < 4 + nk) { dst = s_k; rowb = (p - 4) * 16;      doPhi = true;  }
    else                 { dst = s_v; rowb = (p - 4 - nk) * 16; doPhi = false; }
#pragma unroll
    for (int j = 0; j < 2; j++) {
      int cch = tid + j * 256;
      int r = cch >> 5;
      float4 f = *(const float4*)(zone + cch * 4);
      float o0, o1, o2, o3;
      if (doPhi) {
        o0 = phi_f(f.x, scv.x, biv.x); o1 = phi_f(f.y, scv.y, biv.y);
        o2 = phi_f(f.z, scv.z, biv.z); o3 = phi_f(f.w, scv.w, biv.w);
      } else { o0 = f.x; o1 = f.y; o2 = f.z; o3 = f.w; }
      int rowA = rowb + r;
      int grp = (colf >> 3) ^ (rowA & 7);
      __half2 h0 = __floats2half2_rn(o0, o1), h1 = __floats2half2_rn(o2, o3);
      uint2 pk; pk.x = *(unsigned*)&h0; pk.y = *(unsigned*)&h1;
      *(uint2*)(dst + rowA * 128 + (grp << 3) + (colf & 7)) = pk;
    }
    if (p + 4 < P) issue(p + 4);
  };

  int w = tid >> 5, g = lane >> 2, t4 = lane & 3;
  int mt = w & 3, nh = w >> 2, m0 = mt << 4;
  int jpmax = half ? (2 * (1 - (mt >> 1))) : (2 * ((mt >> 1) + 1));
  float sgn = half ? -1.f : 1.f;
  int l7 = lane & 7, cb3 = lane >> 4, ca3 = (lane >> 3) & 1;

  int rq = m0 + (lane & 15), rq7 = rq & 7;
  unsigned aQbase = sb + (unsigned)(rq * 256);
  int rA = (lane & 7) + 8 * (lane >> 4);
  unsigned bKbase = sb + 16384u + (unsigned)(rA * 256);
  int rB = (lane & 7) + 8 * ((lane >> 3) & 1);
  unsigned bVbase = sb + 32768u + (unsigned)(rB * 256);
  unsigned bSbase = sb + 49152u + (unsigned)(rB * 256);

  float o[8][4];
  float p_[8][4];
#pragma unroll
  for (int jt = 0; jt < 8; jt++) {
    o[jt][0] = o[jt][1] = o[jt][2] = o[jt][3] = 0.f;
    p_[jt][0] = p_[jt][1] = p_[jt][2] = p_[jt][3] = 0.f;
  }

  auto ochunk = [&](int k0c) {  // O += phi_q(:, k0) @ S(k0, nhalf)
    int k0 = k0c * 16;
    unsigned a0, a1, a2, a3;
    ldsm4(a0, a1, a2, a3, aQbase + (unsigned)(((2 * k0c + cb3) ^ rq7) << 4));
#pragma unroll
    for (int jp = 0; jp < 4; jp++) {
      unsigned b0, b1, b2, b3;
      ldsm4t(b0, b1, b2, b3, bSbase + (unsigned)(k0 * 256 + (((nh * 8 + 2 * jp + cb3) ^ l7) << 4)));
      mma16816(o[2 * jp],     a0, a1, a2, a3, b0, b1);
      mma16816(o[2 * jp + 1], a0, a1, a2, a3, b2, b3);
    }
  };
  auto pchunk = [&](int k0c) {  // P += phi_q(:, k0) @ phi_k(:, k0)^T
    if (jpmax == 0) return;
    unsigned a0, a1, a2, a3;
    ldsm4(a0, a1, a2, a3, aQbase + (unsigned)(((2 * k0c + cb3) ^ rq7) << 4));
#pragma unroll
    for (int jp = 0; jp < 4; jp++) {
      if (jp < jpmax) {
        unsigned b0, b1, b2, b3;
        ldsm4(b0, b1, b2, b3, bKbase + (unsigned)(jp * 4096 + (((2 * k0c + ca3) ^ l7) << 4)));
        mma16816(p_[2 * jp],     a0, a1, a2, a3, b0, b1);
        mma16816(p_[2 * jp + 1], a0, a1, a2, a3, b2, b3);
      }
    }
  };

  // Phase A: q pieces
  step(0); step(1); step(2); step(3);
  __syncthreads();

  // den base: phi_q[r] . Z  (4 threads per row, swizzled reads)
  {
    int r = tid >> 2, ds = (tid & 3) << 5;
    float acc = 0.f;
#pragma unroll
    for (int j = 0; j < 16; j++) {
      int col = ds + 2 * j;
      int grp = ((col >> 3) ^ (r & 7));
      float2 f = __half22float2(*(const __half2*)(s_q + r * 128 + (grp << 3) + (col & 7)));
      acc += f.x * s_z[col] + f.y * s_z[col + 1];
    }
    atomicAdd(&s_den[r], acc);
  }

  // Phase B: k pieces interleaved with O chunks 0..3
  if (half == 0) {
    for (int i = 0; i < 4; i++) { step(4 + i); ochunk(i); }
  } else {
    for (int i = 0; i < 2; i++) { step(4 + i); ochunk(2 * i); ochunk(2 * i + 1); }
  }
  __syncthreads();   // k fully staged

  // Phase C: v pieces interleaved with O chunks 4..7 and P chunks 0..7
  if (half == 0) {
    for (int i = 0; i < 4; i++) {
      step(8 + i); ochunk(4 + i); pchunk(2 * i); pchunk(2 * i + 1);
    }
  } else {
    for (int i = 0; i < 2; i++) {
      step(6 + i); ochunk(4 + 2 * i); ochunk(5 + 2 * i);
      pchunk(4 * i); pchunk(4 * i + 1); pchunk(4 * i + 2); pchunk(4 * i + 3);
    }
  }
  __syncthreads();   // v fully staged

  // signed rowsums + signed fp16 pack of P into A fragments
  float rs0 = 0.f, rs1 = 0.f;
  unsigned ph[8][2];
#pragma unroll
  for (int jt = 0; jt < 8; jt++) {
    float v0 = sgn * p_[jt][0], v1 = sgn * p_[jt][1];
    float v2 = sgn * p_[jt][2], v3 = sgn * p_[jt][3];
    rs0 += v0 + v1; rs1 += v2 + v3;
    __half2 h0 = __floats2half2_rn(v0, v1);
    __half2 h1 = __floats2half2_rn(v2, v3);
    ph[jt][0] = *(unsigned*)&h0;
    ph[jt][1] = *(unsigned*)&h1;
  }
  rs0 += __shfl_xor_sync(0xffffffffu, rs0, 1);
  rs0 += __shfl_xor_sync(0xffffffffu, rs0, 2);
  rs1 += __shfl_xor_sync(0xffffffffu, rs1, 1);
  rs1 += __shfl_xor_sync(0xffffffffu, rs1, 2);

  // PV gemm: O +/- = P @ V
#pragma unroll
  for (int kt = 0; kt < 4; kt++) {
    if (kt < jpmax) {
      unsigned a0 = ph[2 * kt][0], a1 = ph[2 * kt][1];
      unsigned a2 = ph[2 * kt + 1][0], a3 = ph[2 * kt + 1][1];
#pragma unroll
      for (int jp = 0; jp < 4; jp++) {
        unsigned b0, b1, b2, b3;
        ldsm4t(b0, b1, b2, b3, bVbase + (unsigned)(kt * 4096 + (((nh * 8 + 2 * jp + cb3) ^ l7) << 4)));
        mma16816(o[2 * jp],     a0, a1, a2, a3, b0, b1);
        mma16816(o[2 * jp + 1], a0, a1, a2, a3, b2, b3);
      }
    }
  }

  // epilogue
  float inv0 = 1.f / fmaxf(s_den[m0 + g]     + rs0, EPS_);
  float inv1 = 1.f / fmaxf(s_den[m0 + g + 8] + rs1, EPS_);
  float* op = out + qoff;
#pragma unroll
  for (int jt = 0; jt < 8; jt++) {
    int n0 = nh * 64 + jt * 8 + 2 * t4;
    float2 v0; v0.x = o[jt][0] * inv0; v0.y = o[jt][1] * inv0;
    float2 v1; v1.x = o[jt][2] * inv1; v1.y = o[jt][3] * inv1;
    *(float2*)(op + (m0 + g) * D_ + n0)     = v0;
    *(float2*)(op + (m0 + g + 8) * D_ + n0) = v1;
  }
}

// ---------------------------------------------------------------------------
#define P1_SMEM 115200
#define P3_SMEM 115456

extern "C" void kernel_launch(void* const* d_in, const int* in_sizes, int n_in,
                              void* d_out, int out_size) {
  (void)in_sizes; (void)n_in; (void)out_size;
  const float* q  = (const float*)d_in[0];
  const float* k  = (const float*)d_in[1];
  const float* v  = (const float*)d_in[2];
  const float* sc = (const float*)d_in[3];
  const float* bi = (const float*)d_in[4];
  float* out = (float*)d_out;

  static bool attrs_set = false;
  if (!attrs_set) {
    cudaFuncSetAttribute(la_pass1, cudaFuncAttributeMaxDynamicSharedMemorySize, P1_SMEM);
    cudaFuncSetAttribute(la_pass3, cudaFuncAttributeMaxDynamicSharedMemorySize, P3_SMEM);
    attrs_set = true;
  }

  la_pass1<<<dim3(NC_, BH_), 256, P1_SMEM>>>(k, v, sc, bi);
  la_pass2<<<(BH_ * D_ * D_ / 8) / 256, 256>>>();
  la_pass3<<<dim3(NC_, BH_, 2), 256, P3_SMEM>>>(q, k, v, sc, bi, out);
}